// round 1
// baseline (speedup 1.0000x reference)
#include <cuda_runtime.h>
#include <math.h>

// Problem constants
#define BATCH 32
#define CDIM  512
#define NDIM  4096
#define TCL   72
#define KCL   64
#define NTILE 128           // n per pass1 block
#define NTILES (NDIM/NTILE) // 32
#define NCHUNKS 8           // split-N for pass2

// Scratch (static device globals; no runtime allocation)
__device__ float g_a2[(size_t)BATCH * TCL * NDIM];                 // assign * invnorm
__device__ float g_massp[(size_t)BATCH * NTILES * TCL];            // partial mass per n-tile
__device__ float g_aggp[(size_t)NCHUNKS * BATCH * KCL * CDIM];     // partial agg per n-chunk

// ---------------------------------------------------------------------------
// Pass 1: per (b, n-tile of 128):
//   raw[t,n] = sum_c W[t,c] x[b,c,n]   (72x512 @ 512x128)
//   ssq[n]   = sum_c x^2
//   assign   = softmax_t(raw*invn + bias)
//   g_a2     = assign * invn ;  g_massp = per-tile sum_n assign
// 256 threads: 8 t-groups (9 t each) x 32 n-lanes (4 n each) -> 36 acc/thread
// ---------------------------------------------------------------------------
__global__ __launch_bounds__(256) void pass1(const float* __restrict__ x,
                                             const float* __restrict__ conv_w,
                                             const float* __restrict__ conv_b)
{
    const int ntile = blockIdx.x;          // 0..31
    const int b     = blockIdx.y;          // 0..31
    const int n0    = ntile * NTILE;
    const int tid   = threadIdx.x;
    const int ng    = tid & 31;            // n lane
    const int tg    = tid >> 5;            // 0..7 -> t in [9*tg, 9*tg+9)

    // Shared buffer, phase-overlapped:
    //  Phase A (GEMM): w_s [32][73] at 0 (2336 floats), x_s [32][128] at 2336 (4096)
    //  Phase B (softmax): lg [72][132] at 0 (9504), invn_s [128] at 9504
    __shared__ float sbuf[TCL * 132 + 128];
    float* w_s = sbuf;                // [cc][t] padded row 73
    float* x_s = sbuf + 32 * 73;      // [cc][n]

    float acc[9][4];
    #pragma unroll
    for (int i = 0; i < 9; i++)
        #pragma unroll
        for (int j = 0; j < 4; j++) acc[i][j] = 0.0f;
    float ssq[4] = {0.f, 0.f, 0.f, 0.f};

    for (int c0 = 0; c0 < CDIM; c0 += 32) {
        __syncthreads();
        // load W chunk transposed: w_s[cc][t]
        for (int i = tid; i < TCL * 32; i += 256) {
            int t = i >> 5, cc = i & 31;
            w_s[cc * 73 + t] = conv_w[t * CDIM + c0 + cc];
        }
        // load x chunk: x_s[cc][n]
        for (int i = tid; i < 32 * NTILE; i += 256) {
            int cc = i >> 7, nn = i & 127;
            x_s[cc * NTILE + nn] = x[((size_t)b * CDIM + c0 + cc) * NDIM + n0 + nn];
        }
        __syncthreads();

        if (tg == 0) {  // warp 0 accumulates column sums of squares
            #pragma unroll
            for (int cc = 0; cc < 32; cc++) {
                #pragma unroll
                for (int j = 0; j < 4; j++) {
                    float v = x_s[cc * NTILE + ng + 32 * j];
                    ssq[j] = fmaf(v, v, ssq[j]);
                }
            }
        }
        #pragma unroll
        for (int cc = 0; cc < 32; cc++) {
            float xv[4];
            #pragma unroll
            for (int j = 0; j < 4; j++) xv[j] = x_s[cc * NTILE + ng + 32 * j];
            #pragma unroll
            for (int i = 0; i < 9; i++) {
                float wv = w_s[cc * 73 + tg * 9 + i];
                #pragma unroll
                for (int j = 0; j < 4; j++) acc[i][j] = fmaf(wv, xv[j], acc[i][j]);
            }
        }
    }
    __syncthreads();

    float* lg     = sbuf;               // [72][132]
    float* invn_s = sbuf + TCL * 132;   // [128]
    if (tg == 0) {
        #pragma unroll
        for (int j = 0; j < 4; j++) {
            float nrm = sqrtf(ssq[j]);
            invn_s[ng + 32 * j] = 1.0f / fmaxf(nrm, 1e-12f);
        }
    }
    __syncthreads();

    // logits into shared
    #pragma unroll
    for (int i = 0; i < 9; i++) {
        int t = tg * 9 + i;
        float bb = conv_b[t];
        #pragma unroll
        for (int j = 0; j < 4; j++) {
            int n = ng + 32 * j;
            lg[t * 132 + n] = fmaf(acc[i][j], invn_s[n], bb);
        }
    }
    __syncthreads();

    // softmax over t (one thread per n)
    if (tid < NTILE) {
        const int n = tid;
        float mx = -1e30f;
        #pragma unroll 8
        for (int t = 0; t < TCL; t++) mx = fmaxf(mx, lg[t * 132 + n]);
        float s = 0.0f;
        #pragma unroll 8
        for (int t = 0; t < TCL; t++) {
            float e = __expf(lg[t * 132 + n] - mx);
            lg[t * 132 + n] = e;
            s += e;
        }
        float inv_s = 1.0f / s;
        float a2s   = inv_s * invn_s[n];
        #pragma unroll 8
        for (int t = 0; t < TCL; t++) {
            float e = lg[t * 132 + n];
            g_a2[((size_t)b * TCL + t) * NDIM + n0 + n] = e * a2s;
            lg[t * 132 + n] = e * inv_s;  // assign, for mass
        }
    }
    __syncthreads();

    // partial mass per cluster (fixed-order deterministic sum)
    if (tid < TCL) {
        float m = 0.0f;
        #pragma unroll 8
        for (int n = 0; n < NTILE; n++) m += lg[tid * 132 + n];
        g_massp[((size_t)b * NTILES + ntile) * TCL + tid] = m;
    }
}

// ---------------------------------------------------------------------------
// Pass 2: agg[b,k,c] = sum_n a2[b,k,n] * x[b,c,n], k < 64 only.
// Grid: (nchunk=8, ctile=4, b=32). Block: k full 64 x c-tile 128, n-chunk 512.
// 256 threads: 8 k-groups (8 k each) x 32 c-lanes (4 c each) -> 32 acc/thread
// ---------------------------------------------------------------------------
__global__ __launch_bounds__(256) void pass2(const float* __restrict__ x)
{
    const int nchunk = blockIdx.x;   // 0..7
    const int ct     = blockIdx.y;   // 0..3
    const int b      = blockIdx.z;   // 0..31
    const int c0     = ct * 128;
    const int tid    = threadIdx.x;
    const int cg     = tid & 31;     // c lane
    const int kg     = tid >> 5;     // 0..7 -> k in [8*kg, 8*kg+8)

    __shared__ float a2_s[KCL * 32];     // [k][nn]
    __shared__ float x_s[128 * 33];      // [c][nn] padded

    float acc[8][4];
    #pragma unroll
    for (int i = 0; i < 8; i++)
        #pragma unroll
        for (int j = 0; j < 4; j++) acc[i][j] = 0.0f;

    for (int nb = 0; nb < 16; nb++) {
        const int n0 = nchunk * 512 + nb * 32;
        __syncthreads();
        for (int i = tid; i < KCL * 32; i += 256) {
            int k = i >> 5, nn = i & 31;
            a2_s[k * 32 + nn] = g_a2[((size_t)b * TCL + k) * NDIM + n0 + nn];
        }
        for (int i = tid; i < 128 * 32; i += 256) {
            int c = i >> 5, nn = i & 31;
            x_s[c * 33 + nn] = x[((size_t)b * CDIM + c0 + c) * NDIM + n0 + nn];
        }
        __syncthreads();
        #pragma unroll
        for (int nn = 0; nn < 32; nn++) {
            float xv[4];
            #pragma unroll
            for (int j = 0; j < 4; j++) xv[j] = x_s[(cg + 32 * j) * 33 + nn];
            #pragma unroll
            for (int i = 0; i < 8; i++) {
                float av = a2_s[(kg * 8 + i) * 32 + nn];
                #pragma unroll
                for (int j = 0; j < 4; j++) acc[i][j] = fmaf(av, xv[j], acc[i][j]);
            }
        }
    }
    #pragma unroll
    for (int i = 0; i < 8; i++) {
        int k = kg * 8 + i;
        #pragma unroll
        for (int j = 0; j < 4; j++) {
            g_aggp[(((size_t)nchunk * BATCH + b) * KCL + k) * CDIM + c0 + cg + 32 * j] = acc[i][j];
        }
    }
}

// ---------------------------------------------------------------------------
// Pass 3: per (b,k): v = sum_chunks agg_part - centroid*mass;
//         out = v / (max(||v||,eps) * 8)   (attn & global norm cancel, see theory)
// ---------------------------------------------------------------------------
__global__ __launch_bounds__(128) void pass3(const float* __restrict__ centroids,
                                             float* __restrict__ out)
{
    const int k   = blockIdx.x;   // 0..63
    const int b   = blockIdx.y;   // 0..31
    const int tid = threadIdx.x;

    __shared__ float s_mass;
    __shared__ float s_red[4];

    if (tid == 0) {
        float m = 0.0f;
        #pragma unroll 8
        for (int t = 0; t < NTILES; t++) m += g_massp[((size_t)b * NTILES + t) * TCL + k];
        s_mass = m;
    }
    __syncthreads();
    const float mass = s_mass;

    float v[4];
    float ssq = 0.0f;
    #pragma unroll
    for (int j = 0; j < 4; j++) {
        int c = tid + 128 * j;
        float a = 0.0f;
        #pragma unroll
        for (int ch = 0; ch < NCHUNKS; ch++)
            a += g_aggp[(((size_t)ch * BATCH + b) * KCL + k) * CDIM + c];
        float val = a - centroids[k * CDIM + c] * mass;
        v[j] = val;
        ssq = fmaf(val, val, ssq);
    }
    #pragma unroll
    for (int o = 16; o > 0; o >>= 1) ssq += __shfl_xor_sync(0xffffffffu, ssq, o);
    if ((tid & 31) == 0) s_red[tid >> 5] = ssq;
    __syncthreads();
    float tot = s_red[0] + s_red[1] + s_red[2] + s_red[3];
    float scale = 1.0f / (fmaxf(sqrtf(tot), 1e-12f) * 8.0f);
    #pragma unroll
    for (int j = 0; j < 4; j++)
        out[((size_t)b * KCL + k) * CDIM + tid + 128 * j] = v[j] * scale;
}

// ---------------------------------------------------------------------------
extern "C" void kernel_launch(void* const* d_in, const int* in_sizes, int n_in,
                              void* d_out, int out_size)
{
    const float* x         = (const float*)d_in[0];  // [32,512,4096]
    const float* centroids = (const float*)d_in[1];  // [72,512]
    const float* conv_w    = (const float*)d_in[2];  // [72,512]
    const float* conv_b    = (const float*)d_in[3];  // [72]
    // d_in[4..8] (ghost_weights, w1, b1, w2, b2) provably cancel; unused.
    float* out = (float*)d_out;                      // [32, 64*512]

    pass1<<<dim3(NTILES, BATCH), 256>>>(x, conv_w, conv_b);
    pass2<<<dim3(NCHUNKS, 4, BATCH), 256>>>(x);
    pass3<<<dim3(KCL, BATCH), 128>>>(centroids, out);
}

// round 2
// speedup vs baseline: 1.4147x; 1.4147x over previous
#include <cuda_runtime.h>
#include <math.h>

// Problem constants
#define BATCH 32
#define CDIM  512
#define NDIM  4096
#define TCL   72
#define KCL   64
#define NTILE 128           // n per pass1 block
#define NTILES (NDIM/NTILE) // 32
#define NCHUNKS 8           // split-N for pass2

// Scratch (static device globals; no runtime allocation)
__device__ float g_a2[(size_t)BATCH * TCL * NDIM];                 // assign * invnorm
__device__ float g_massp[(size_t)BATCH * NTILES * TCL];            // partial mass per n-tile
__device__ float g_aggp[(size_t)NCHUNKS * BATCH * KCL * CDIM];     // partial agg per n-chunk

typedef unsigned long long ull;

// ---- f32x2 packed helpers -------------------------------------------------
__device__ __forceinline__ void fma2(ull& d, ull a, ull b) {
    asm("fma.rn.f32x2 %0, %1, %2, %0;" : "+l"(d) : "l"(a), "l"(b));
}
__device__ __forceinline__ ull pack2(float lo, float hi) {
    ull r; asm("mov.b64 %0, {%1,%2};" : "=l"(r) : "f"(lo), "f"(hi)); return r;
}
__device__ __forceinline__ ull dup2(float v) { return pack2(v, v); }
__device__ __forceinline__ float2 unpack2(ull p) {
    float2 r; asm("mov.b64 {%0,%1}, %2;" : "=f"(r.x), "=f"(r.y) : "l"(p)); return r;
}

// ---------------------------------------------------------------------------
// Pass 1: per (b, n-tile of 128):
//   raw[t,n] = sum_c W[t,c] x[b,c,n];  ssq[n] = sum_c x^2
//   assign = softmax_t(raw*invn + bias); g_a2 = assign*invn; g_massp = sum_n
// 256 thr: tg=tid>>5 covers 9 t; ng=tid&31 covers n pairs {2ng,2ng+1},{+64,+65}
// acc packed f32x2 along n: 18 x 64-bit accumulators.
// ---------------------------------------------------------------------------
__global__ __launch_bounds__(256, 2) void pass1(const float* __restrict__ x,
                                                const float* __restrict__ conv_w,
                                                const float* __restrict__ conv_b)
{
    const int ntile = blockIdx.x;
    const int b     = blockIdx.y;
    const int n0    = ntile * NTILE;
    const int tid   = threadIdx.x;
    const int ng    = tid & 31;
    const int tg    = tid >> 5;

    // Phase A (GEMM): w_s [72][32] at 0 (2304), x_s [32][128] at 2304 (4096)
    // Phase B (softmax): lg [72][132] at 0 (9504), invn_s [128] at 9504
    __shared__ __align__(16) float sbuf[TCL * 132 + 128];
    float* w_s = sbuf;            // [t][cc]
    float* x_s = sbuf + TCL * 32; // [cc][n]

    ull acc[9][2];
    #pragma unroll
    for (int i = 0; i < 9; i++) { acc[i][0] = 0ull; acc[i][1] = 0ull; }
    ull ss0 = 0ull, ss1 = 0ull;

    for (int c0 = 0; c0 < CDIM; c0 += 32) {
        __syncthreads();
        // W chunk: [t][cc], float4 (rows of 32 floats = 8 float4)
        for (int i = tid; i < TCL * 8; i += 256) {
            int t = i >> 3, q = i & 7;
            ((float4*)w_s)[i] = *(const float4*)(conv_w + t * CDIM + c0 + 4 * q);
        }
        // x chunk: [cc][n], float4 (rows of 128 floats = 32 float4)
        for (int i = tid; i < 32 * 32; i += 256) {
            int cc = i >> 5, q = i & 31;
            ((float4*)x_s)[i] =
                *(const float4*)(x + ((size_t)b * CDIM + c0 + cc) * NDIM + n0 + 4 * q);
        }
        __syncthreads();

        #pragma unroll
        for (int cc = 0; cc < 32; cc++) {
            ull xv0 = *(const ull*)&x_s[cc * NTILE + 2 * ng];
            ull xv1 = *(const ull*)&x_s[cc * NTILE + 2 * ng + 64];
            if (tg == 0) { fma2(ss0, xv0, xv0); fma2(ss1, xv1, xv1); }
            #pragma unroll
            for (int i = 0; i < 9; i++) {
                ull wp = dup2(w_s[(tg * 9 + i) * 32 + cc]);
                fma2(acc[i][0], wp, xv0);
                fma2(acc[i][1], wp, xv1);
            }
        }
    }
    __syncthreads();

    float* lg     = sbuf;             // [72][132]
    float* invn_s = sbuf + TCL * 132; // [128]
    if (tg == 0) {
        float2 s0 = unpack2(ss0), s1 = unpack2(ss1);
        invn_s[2 * ng]      = 1.0f / fmaxf(sqrtf(s0.x), 1e-12f);
        invn_s[2 * ng + 1]  = 1.0f / fmaxf(sqrtf(s0.y), 1e-12f);
        invn_s[2 * ng + 64] = 1.0f / fmaxf(sqrtf(s1.x), 1e-12f);
        invn_s[2 * ng + 65] = 1.0f / fmaxf(sqrtf(s1.y), 1e-12f);
    }
    __syncthreads();

    {
        ull inv0 = *(const ull*)&invn_s[2 * ng];
        ull inv1 = *(const ull*)&invn_s[2 * ng + 64];
        #pragma unroll
        for (int i = 0; i < 9; i++) {
            int t = tg * 9 + i;
            ull b0 = dup2(conv_b[t]);
            ull b1 = b0;
            fma2(b0, acc[i][0], inv0);
            fma2(b1, acc[i][1], inv1);
            *(ull*)&lg[t * 132 + 2 * ng]      = b0;
            *(ull*)&lg[t * 132 + 2 * ng + 64] = b1;
        }
    }
    __syncthreads();

    // softmax over t (one thread per n)
    if (tid < NTILE) {
        const int n = tid;
        float mx = -1e30f;
        #pragma unroll 8
        for (int t = 0; t < TCL; t++) mx = fmaxf(mx, lg[t * 132 + n]);
        float s = 0.0f;
        #pragma unroll 8
        for (int t = 0; t < TCL; t++) {
            float e = __expf(lg[t * 132 + n] - mx);
            lg[t * 132 + n] = e;
            s += e;
        }
        float inv_s = 1.0f / s;
        float a2s   = inv_s * invn_s[n];
        #pragma unroll 8
        for (int t = 0; t < TCL; t++) {
            float e = lg[t * 132 + n];
            g_a2[((size_t)b * TCL + t) * NDIM + n0 + n] = e * a2s;
            lg[t * 132 + n] = e * inv_s;  // assign, for mass
        }
    }
    __syncthreads();

    // partial mass per cluster (fixed-order deterministic sum)
    if (tid < TCL) {
        float m = 0.0f;
        #pragma unroll 8
        for (int n = 0; n < NTILE; n++) m += lg[tid * 132 + n];
        g_massp[((size_t)b * NTILES + ntile) * TCL + tid] = m;
    }
}

// ---------------------------------------------------------------------------
// Pass 2: agg[b,k,c] = sum_n a2[b,k,n] * x[b,c,n], k < 64 only.
// Grid: (nchunk=8, ctile=4, b=32). Block: 64 k x 128 c, n-chunk 512.
// 256 thr: kg=tid>>5 covers 8 k (4 f32x2 pairs via a2_s[nn][k] LDS.64 broadcast),
// cg=tid&31 covers 4 c (duplicated). acc = 16 x 64-bit.
// ---------------------------------------------------------------------------
__global__ __launch_bounds__(256, 2) void pass2(const float* __restrict__ x)
{
    const int nchunk = blockIdx.x;
    const int ct     = blockIdx.y;
    const int b      = blockIdx.z;
    const int c0     = ct * 128;
    const int tid    = threadIdx.x;
    const int cg     = tid & 31;
    const int kg     = tid >> 5;

    __shared__ __align__(16) float x_s[128 * 33]; // [c][nn] pad 33 (conflict-free reads)
    __shared__ __align__(16) float a2_s[32 * 66]; // [nn][k] pad 66 (8B-aligned k pairs)

    ull acc[4][4];
    #pragma unroll
    for (int i = 0; i < 4; i++)
        #pragma unroll
        for (int j = 0; j < 4; j++) acc[i][j] = 0ull;

    for (int nb = 0; nb < 16; nb++) {
        const int n0 = nchunk * 512 + nb * 32;
        __syncthreads();
        // a2 transpose: [nn][k]
        for (int i = tid; i < KCL * 32; i += 256) {
            int k = i >> 5, nn = i & 31;
            a2_s[nn * 66 + k] = g_a2[((size_t)b * TCL + k) * NDIM + n0 + nn];
        }
        // x: [c][nn]
        for (int i = tid; i < 128 * 32; i += 256) {
            int c = i >> 5, nn = i & 31;
            x_s[c * 33 + nn] = x[((size_t)b * CDIM + c0 + c) * NDIM + n0 + nn];
        }
        __syncthreads();
        #pragma unroll
        for (int nn = 0; nn < 32; nn++) {
            ull ap[4];
            #pragma unroll
            for (int i = 0; i < 4; i++)
                ap[i] = *(const ull*)&a2_s[nn * 66 + kg * 8 + 2 * i];
            #pragma unroll
            for (int j = 0; j < 4; j++) {
                ull xp = dup2(x_s[(cg + 32 * j) * 33 + nn]);
                #pragma unroll
                for (int i = 0; i < 4; i++) fma2(acc[i][j], ap[i], xp);
            }
        }
    }
    #pragma unroll
    for (int i = 0; i < 4; i++) {
        int k = kg * 8 + 2 * i;
        #pragma unroll
        for (int j = 0; j < 4; j++) {
            float2 v = unpack2(acc[i][j]);
            size_t base = (((size_t)nchunk * BATCH + b) * KCL + k) * CDIM + c0 + cg + 32 * j;
            g_aggp[base]        = v.x;
            g_aggp[base + CDIM] = v.y;
        }
    }
}

// ---------------------------------------------------------------------------
// Pass 3: per (b,k): v = sum_chunks agg_part - centroid*mass;
//         out = v / (max(||v||,eps) * 8)   (attn & global norm cancel)
// ---------------------------------------------------------------------------
__global__ __launch_bounds__(128) void pass3(const float* __restrict__ centroids,
                                             float* __restrict__ out)
{
    const int k   = blockIdx.x;
    const int b   = blockIdx.y;
    const int tid = threadIdx.x;

    __shared__ float s_mass;
    __shared__ float s_red[4];

    if (tid == 0) {
        float m = 0.0f;
        #pragma unroll 8
        for (int t = 0; t < NTILES; t++) m += g_massp[((size_t)b * NTILES + t) * TCL + k];
        s_mass = m;
    }
    __syncthreads();
    const float mass = s_mass;

    float v[4];
    float ssq = 0.0f;
    #pragma unroll
    for (int j = 0; j < 4; j++) {
        int c = tid + 128 * j;
        float a = 0.0f;
        #pragma unroll
        for (int ch = 0; ch < NCHUNKS; ch++)
            a += g_aggp[(((size_t)ch * BATCH + b) * KCL + k) * CDIM + c];
        float val = a - centroids[k * CDIM + c] * mass;
        v[j] = val;
        ssq = fmaf(val, val, ssq);
    }
    #pragma unroll
    for (int o = 16; o > 0; o >>= 1) ssq += __shfl_xor_sync(0xffffffffu, ssq, o);
    if ((tid & 31) == 0) s_red[tid >> 5] = ssq;
    __syncthreads();
    float tot = s_red[0] + s_red[1] + s_red[2] + s_red[3];
    float scale = 1.0f / (fmaxf(sqrtf(tot), 1e-12f) * 8.0f);
    #pragma unroll
    for (int j = 0; j < 4; j++)
        out[((size_t)b * KCL + k) * CDIM + tid + 128 * j] = v[j] * scale;
}

// ---------------------------------------------------------------------------
extern "C" void kernel_launch(void* const* d_in, const int* in_sizes, int n_in,
                              void* d_out, int out_size)
{
    const float* x         = (const float*)d_in[0];  // [32,512,4096]
    const float* centroids = (const float*)d_in[1];  // [72,512]
    const float* conv_w    = (const float*)d_in[2];  // [72,512]
    const float* conv_b    = (const float*)d_in[3];  // [72]
    // d_in[4..8] (ghost_weights, w1, b1, w2, b2) provably cancel; unused.
    float* out = (float*)d_out;                      // [32, 64*512]

    pass1<<<dim3(NTILES, BATCH), 256>>>(x, conv_w, conv_b);
    pass2<<<dim3(NCHUNKS, 4, BATCH), 256>>>(x);
    pass3<<<dim3(KCL, BATCH), 128>>>(centroids, out);
}

// round 3
// speedup vs baseline: 1.9126x; 1.3520x over previous
#include <cuda_runtime.h>
#include <math.h>

#define BATCH 32
#define CDIM  512
#define NDIM  4096
#define TCL   72
#define KCL   64
#define NT1   256            // pass1 n-tile
#define NTILES (NDIM/NT1)    // 16
#define NCHUNKS 8            // pass2 split-N

// Scratch (static device globals; no runtime allocation)
__device__ float g_a2[(size_t)BATCH * KCL * NDIM];              // assign*invnorm, k<64 only
__device__ float g_massp[(size_t)BATCH * NTILES * TCL];
__device__ float g_aggp[(size_t)NCHUNKS * BATCH * KCL * CDIM];

typedef unsigned long long ull;

__device__ __forceinline__ void fma2(ull& d, ull a, ull b) {
    asm("fma.rn.f32x2 %0, %1, %2, %0;" : "+l"(d) : "l"(a), "l"(b));
}
__device__ __forceinline__ ull pack2(float lo, float hi) {
    ull r; asm("mov.b64 %0, {%1,%2};" : "=l"(r) : "f"(lo), "f"(hi)); return r;
}
__device__ __forceinline__ ull dup2(float v) { return pack2(v, v); }
__device__ __forceinline__ float2 unpack2(ull p) {
    float2 r; asm("mov.b64 {%0,%1}, %2;" : "=f"(r.x), "=f"(r.y) : "l"(p)); return r;
}
__device__ __forceinline__ unsigned smem_u32(const void* p) {
    unsigned a;
    asm("{ .reg .u64 t; cvta.to.shared.u64 t, %1; cvt.u32.u64 %0, t; }" : "=r"(a) : "l"(p));
    return a;
}
__device__ __forceinline__ void cpa16(unsigned dst, const float* src) {
    asm volatile("cp.async.cg.shared.global [%0], [%1], 16;" :: "r"(dst), "l"(src));
}
__device__ __forceinline__ void cpa8(unsigned dst, const float* src) {
    asm volatile("cp.async.ca.shared.global [%0], [%1], 8;" :: "r"(dst), "l"(src));
}
#define CP_COMMIT() asm volatile("cp.async.commit_group;")
#define CP_WAIT0()  asm volatile("cp.async.wait_group 0;" ::: "memory")

// ---------------------------------------------------------------------------
// Pass 1: logits GEMM (72x512 @ 512x256 per block) + softmax + a2/mass.
// Double-buffered cp.async on x; W pre-duplicated float2 in smem.
// 256 thr: tg=tid>>5 -> 9 t each; ng=tid&31 -> 4 n-pairs.
// smem (dyn 102400B): wd[2] @0/4608, xs[2] @9216/17408 | phaseB: lg@0 (72x260), invn@18720
// ---------------------------------------------------------------------------
__global__ __launch_bounds__(256, 2) void pass1(const float* __restrict__ x,
                                                const float* __restrict__ conv_w,
                                                const float* __restrict__ conv_b)
{
    extern __shared__ __align__(16) float sb[];
    const int ntile = blockIdx.x;
    const int b     = blockIdx.y;
    const int n0    = ntile * NT1;
    const int tid   = threadIdx.x;
    const int ng    = tid & 31;
    const int tg    = tid >> 5;
    const unsigned sbase = smem_u32(sb);

    float* wd0 = sb;
    float* wd1 = sb + 4608;
    float* xs0 = sb + 9216;
    float* xs1 = sb + 17408;

    // prefetch chunk 0
    {
        const float* xsrc = x + (size_t)b * CDIM * NDIM + n0;
        #pragma unroll
        for (int r = 0; r < 8; r++) {
            int i = tid + 256 * r, cc = i >> 6, q = i & 63;
            cpa16(sbase + (9216 + cc * 256 + 4 * q) * 4, xsrc + (size_t)cc * NDIM + 4 * q);
        }
        CP_COMMIT();
        for (int i = tid; i < 576; i += 256) {
            int t = i >> 3, q = i & 7;
            float4 v = *(const float4*)(conv_w + t * CDIM + 4 * q);
            float2* d = (float2*)&wd0[(t * 32 + 4 * q) * 2];
            d[0] = make_float2(v.x, v.x); d[1] = make_float2(v.y, v.y);
            d[2] = make_float2(v.z, v.z); d[3] = make_float2(v.w, v.w);
        }
    }

    ull acc[9][4];
    #pragma unroll
    for (int i = 0; i < 9; i++)
        #pragma unroll
        for (int j = 0; j < 4; j++) acc[i][j] = 0ull;
    ull ssq[4] = {0ull, 0ull, 0ull, 0ull};

    int p = 0;
    for (int ch = 0; ch < 16; ch++) {
        CP_WAIT0();
        __syncthreads();
        if (ch < 15) {
            const int c0n = (ch + 1) * 32;
            const float* xsrc = x + ((size_t)b * CDIM + c0n) * NDIM + n0;
            const unsigned xdst = sbase + (9216 + (1 - p) * 8192) * 4;
            #pragma unroll
            for (int r = 0; r < 8; r++) {
                int i = tid + 256 * r, cc = i >> 6, q = i & 63;
                cpa16(xdst + (cc * 256 + 4 * q) * 4, xsrc + (size_t)cc * NDIM + 4 * q);
            }
        }
        CP_COMMIT();
        if (ch < 15) {
            const int c0n = (ch + 1) * 32;
            float* wdn = (p == 0) ? wd1 : wd0;
            for (int i = tid; i < 576; i += 256) {
                int t = i >> 3, q = i & 7;
                float4 v = *(const float4*)(conv_w + t * CDIM + c0n + 4 * q);
                float2* d = (float2*)&wdn[(t * 32 + 4 * q) * 2];
                d[0] = make_float2(v.x, v.x); d[1] = make_float2(v.y, v.y);
                d[2] = make_float2(v.z, v.z); d[3] = make_float2(v.w, v.w);
            }
        }
        const float* xb = (p == 0) ? xs0 : xs1;
        const float* wb = (p == 0) ? wd0 : wd1;
        #pragma unroll 4
        for (int cc = 0; cc < 32; cc++) {
            ull xv[4];
            #pragma unroll
            for (int j = 0; j < 4; j++)
                xv[j] = *(const ull*)&xb[cc * 256 + 2 * ng + 64 * j];
            if (tg == 0) {
                #pragma unroll
                for (int j = 0; j < 4; j++) fma2(ssq[j], xv[j], xv[j]);
            }
            #pragma unroll
            for (int i = 0; i < 9; i++) {
                ull wp = *(const ull*)&wb[((tg * 9 + i) * 32 + cc) * 2];
                #pragma unroll
                for (int j = 0; j < 4; j++) fma2(acc[i][j], wp, xv[j]);
            }
        }
        p ^= 1;
    }
    __syncthreads();

    float* lg     = sb;            // [72][260]
    float* invn_s = sb + 18720;    // [256]
    if (tg == 0) {
        #pragma unroll
        for (int j = 0; j < 4; j++) {
            float2 s = unpack2(ssq[j]);
            invn_s[2 * ng + 64 * j]     = 1.0f / fmaxf(sqrtf(s.x), 1e-12f);
            invn_s[2 * ng + 64 * j + 1] = 1.0f / fmaxf(sqrtf(s.y), 1e-12f);
        }
    }
    __syncthreads();
    {
        ull inv[4];
        #pragma unroll
        for (int j = 0; j < 4; j++) inv[j] = *(const ull*)&invn_s[2 * ng + 64 * j];
        #pragma unroll
        for (int i = 0; i < 9; i++) {
            int t = tg * 9 + i;
            ull bd = dup2(conv_b[t]);
            #pragma unroll
            for (int j = 0; j < 4; j++) {
                ull l = bd;
                fma2(l, acc[i][j], inv[j]);
                *(ull*)&lg[t * 260 + 2 * ng + 64 * j] = l;
            }
        }
    }
    __syncthreads();

    // softmax over t, thread per n (all 256 threads)
    {
        const int n = tid;
        float mx = -1e30f;
        #pragma unroll 8
        for (int t = 0; t < TCL; t++) mx = fmaxf(mx, lg[t * 260 + n]);
        float s = 0.0f;
        #pragma unroll 8
        for (int t = 0; t < TCL; t++) {
            float e = __expf(lg[t * 260 + n] - mx);
            lg[t * 260 + n] = e;
            s += e;
        }
        float inv_s = 1.0f / s;
        float a2s   = inv_s * invn_s[n];
        float* gp   = &g_a2[(size_t)b * KCL * NDIM + n0 + n];
        #pragma unroll 8
        for (int t = 0; t < TCL; t++) {
            float e = lg[t * 260 + n];
            if (t < KCL) gp[(size_t)t * NDIM] = e * a2s;
            lg[t * 260 + n] = e * inv_s;
        }
    }
    __syncthreads();
    if (tid < TCL) {
        float m = 0.0f;
        #pragma unroll 8
        for (int n = 0; n < NT1; n++) m += lg[tid * 260 + n];
        g_massp[((size_t)b * NTILES + ntile) * TCL + tid] = m;
    }
}

// ---------------------------------------------------------------------------
// Pass 2: agg[b,k,c] = sum_n a2[k,n]*x[c,n]. Reduction-dim f32x2 packing:
// acc lanes = even/odd-n partials. No transposes, no dup movs.
// Grid (8 nchunk, 4 ct, 32 b); 256 thr: kg=tid>>5 -> 8 k each; cg -> 4 c each.
// smem (dyn 51200B): a2s[2] @0/2048, xs[2] @4096/8448 (rows pad 34)
// ---------------------------------------------------------------------------
__global__ __launch_bounds__(256, 2) void pass2(const float* __restrict__ x)
{
    extern __shared__ __align__(16) float sb[];
    const int nchunk = blockIdx.x;
    const int ct     = blockIdx.y;
    const int b      = blockIdx.z;
    const int c0     = ct * 128;
    const int tid    = threadIdx.x;
    const int cg     = tid & 31;
    const int kg     = tid >> 5;
    const unsigned sbase = smem_u32(sb);

    const float* a2src = g_a2 + (size_t)b * KCL * NDIM;
    const float* xsrc0 = x + ((size_t)b * CDIM + c0) * NDIM;

    // prefetch chunk 0
    {
        const int n0 = nchunk * 512;
        #pragma unroll
        for (int r = 0; r < 2; r++) {
            int i = tid + 256 * r, k = i >> 3, q = i & 7;
            cpa16(sbase + (k * 32 + 4 * q) * 4, a2src + (size_t)k * NDIM + n0 + 4 * q);
        }
        #pragma unroll
        for (int r = 0; r < 8; r++) {
            int i = tid + 256 * r, c = i >> 4, h = i & 15;
            cpa8(sbase + (4096 + c * 34 + 2 * h) * 4, xsrc0 + (size_t)c * NDIM + n0 + 2 * h);
        }
        CP_COMMIT();
    }

    ull acc[8][4];
    #pragma unroll
    for (int i = 0; i < 8; i++)
        #pragma unroll
        for (int j = 0; j < 4; j++) acc[i][j] = 0ull;

    int p = 0;
    for (int nb = 0; nb < 16; nb++) {
        CP_WAIT0();
        __syncthreads();
        if (nb < 15) {
            const int n0 = nchunk * 512 + (nb + 1) * 32;
            const unsigned adst = sbase + ((1 - p) * 2048) * 4;
            const unsigned xdst = sbase + (4096 + (1 - p) * 4352) * 4;
            #pragma unroll
            for (int r = 0; r < 2; r++) {
                int i = tid + 256 * r, k = i >> 3, q = i & 7;
                cpa16(adst + (k * 32 + 4 * q) * 4, a2src + (size_t)k * NDIM + n0 + 4 * q);
            }
            #pragma unroll
            for (int r = 0; r < 8; r++) {
                int i = tid + 256 * r, c = i >> 4, h = i & 15;
                cpa8(xdst + (c * 34 + 2 * h) * 4, xsrc0 + (size_t)c * NDIM + n0 + 2 * h);
            }
        }
        CP_COMMIT();

        const float* a2b = sb + p * 2048;
        const float* xb  = sb + 4096 + p * 4352;
        #pragma unroll 4
        for (int pr = 0; pr < 16; pr++) {
            ull xv[4];
            #pragma unroll
            for (int j = 0; j < 4; j++)
                xv[j] = *(const ull*)&xb[(cg + 32 * j) * 34 + 2 * pr];
            #pragma unroll
            for (int i = 0; i < 8; i++) {
                ull av = *(const ull*)&a2b[(kg * 8 + i) * 32 + 2 * pr];
                #pragma unroll
                for (int j = 0; j < 4; j++) fma2(acc[i][j], av, xv[j]);
            }
        }
        p ^= 1;
    }

    #pragma unroll
    for (int i = 0; i < 8; i++) {
        int k = kg * 8 + i;
        #pragma unroll
        for (int j = 0; j < 4; j++) {
            float2 v = unpack2(acc[i][j]);
            g_aggp[(((size_t)nchunk * BATCH + b) * KCL + k) * CDIM + c0 + cg + 32 * j] = v.x + v.y;
        }
    }
}

// ---------------------------------------------------------------------------
// Pass 3: v = sum_chunks aggp - centroid*mass; out = v/(max(||v||,eps)*8)
// (attention, ghost weighting and global norm cancel algebraically)
// ---------------------------------------------------------------------------
__global__ __launch_bounds__(128) void pass3(const float* __restrict__ centroids,
                                             float* __restrict__ out)
{
    const int k   = blockIdx.x;
    const int b   = blockIdx.y;
    const int tid = threadIdx.x;

    __shared__ float s_mass;
    __shared__ float s_red[4];

    if (tid == 0) {
        float m = 0.0f;
        #pragma unroll
        for (int t = 0; t < NTILES; t++) m += g_massp[((size_t)b * NTILES + t) * TCL + k];
        s_mass = m;
    }
    __syncthreads();
    const float mass = s_mass;

    float v[4];
    float ssq = 0.0f;
    #pragma unroll
    for (int j = 0; j < 4; j++) {
        int c = tid + 128 * j;
        float a = 0.0f;
        #pragma unroll
        for (int ch = 0; ch < NCHUNKS; ch++)
            a += g_aggp[(((size_t)ch * BATCH + b) * KCL + k) * CDIM + c];
        float val = a - centroids[k * CDIM + c] * mass;
        v[j] = val;
        ssq = fmaf(val, val, ssq);
    }
    #pragma unroll
    for (int o = 16; o > 0; o >>= 1) ssq += __shfl_xor_sync(0xffffffffu, ssq, o);
    if ((tid & 31) == 0) s_red[tid >> 5] = ssq;
    __syncthreads();
    float tot = s_red[0] + s_red[1] + s_red[2] + s_red[3];
    float scale = 1.0f / (fmaxf(sqrtf(tot), 1e-12f) * 8.0f);
    #pragma unroll
    for (int j = 0; j < 4; j++)
        out[((size_t)b * KCL + k) * CDIM + tid + 128 * j] = v[j] * scale;
}

// ---------------------------------------------------------------------------
extern "C" void kernel_launch(void* const* d_in, const int* in_sizes, int n_in,
                              void* d_out, int out_size)
{
    const float* x         = (const float*)d_in[0];
    const float* centroids = (const float*)d_in[1];
    const float* conv_w    = (const float*)d_in[2];
    const float* conv_b    = (const float*)d_in[3];
    float* out = (float*)d_out;

    cudaFuncSetAttribute(pass1, cudaFuncAttributeMaxDynamicSharedMemorySize, 102400);
    cudaFuncSetAttribute(pass2, cudaFuncAttributeMaxDynamicSharedMemorySize, 51200);

    pass1<<<dim3(NTILES, BATCH), 256, 102400>>>(x, conv_w, conv_b);
    pass2<<<dim3(NCHUNKS, 4, BATCH), 256, 51200>>>(x);
    pass3<<<dim3(KCL, BATCH), 128>>>(centroids, out);
}

// round 6
// speedup vs baseline: 2.0677x; 1.0811x over previous
#include <cuda_runtime.h>
#include <cuda_bf16.h>
#include <math.h>
#include <stdint.h>

#define BATCH 32
#define CDIM  512
#define NDIM  4096
#define TCL   72
#define KCL   64
#define NT1   256            // pass1 n-tile
#define NTILES (NDIM/NT1)    // 16

// Scratch (static device globals; no runtime allocation)
__device__ __nv_bfloat16 g_a2h[(size_t)BATCH * KCL * NDIM];
__device__ __nv_bfloat16 g_a2l[(size_t)BATCH * KCL * NDIM];
__device__ float g_massp[(size_t)BATCH * NTILES * TCL];
__device__ float g_agg[(size_t)BATCH * KCL * CDIM];

typedef unsigned long long ull;

// ---- f32x2 packed helpers ---------------------------------------------------
__device__ __forceinline__ void fma2(ull& d, ull a, ull b) {
    asm("fma.rn.f32x2 %0, %1, %2, %0;" : "+l"(d) : "l"(a), "l"(b));
}
__device__ __forceinline__ ull pack2(float lo, float hi) {
    ull r; asm("mov.b64 %0, {%1,%2};" : "=l"(r) : "f"(lo), "f"(hi)); return r;
}
__device__ __forceinline__ ull dup2(float v) { return pack2(v, v); }
__device__ __forceinline__ float2 unpack2(ull p) {
    float2 r; asm("mov.b64 {%0,%1}, %2;" : "=f"(r.x), "=f"(r.y) : "l"(p)); return r;
}
__device__ __forceinline__ unsigned smem_u32(const void* p) {
    unsigned a;
    asm("{ .reg .u64 t; cvta.to.shared.u64 t, %1; cvt.u32.u64 %0, t; }" : "=r"(a) : "l"(p));
    return a;
}
__device__ __forceinline__ void cpa16(unsigned dst, const float* src) {
    asm volatile("cp.async.cg.shared.global [%0], [%1], 16;" :: "r"(dst), "l"(src));
}
#define CP_COMMIT() asm volatile("cp.async.commit_group;")
#define CP_WAIT0()  asm volatile("cp.async.wait_group 0;" ::: "memory")

// ---- mma.sync helpers (plain sm_80+ PTX; no sm_103a-gated features) ---------
__device__ __forceinline__ void ldsm_x4(uint32_t* r, unsigned addr) {
    asm volatile("ldmatrix.sync.aligned.m8n8.x4.shared.b16 {%0,%1,%2,%3}, [%4];"
                 : "=r"(r[0]), "=r"(r[1]), "=r"(r[2]), "=r"(r[3]) : "r"(addr));
}
__device__ __forceinline__ void mma_bf16(float* c, const uint32_t* a, const uint32_t* b) {
    asm volatile(
        "mma.sync.aligned.m16n8k16.row.col.f32.bf16.bf16.f32 "
        "{%0,%1,%2,%3},{%4,%5,%6,%7},{%8,%9},{%0,%1,%2,%3};"
        : "+f"(c[0]), "+f"(c[1]), "+f"(c[2]), "+f"(c[3])
        : "r"(a[0]), "r"(a[1]), "r"(a[2]), "r"(a[3]), "r"(b[0]), "r"(b[1]));
}
__device__ __forceinline__ unsigned swz(unsigned off) { return off ^ ((off >> 3) & 0x70); }

// ---------------------------------------------------------------------------
// Pass 1: logits GEMM + softmax + a2(bf16 hi/lo)/mass.  (SIMT f32x2, cp.async)
// ---------------------------------------------------------------------------
__global__ __launch_bounds__(256, 2) void pass1(const float* __restrict__ x,
                                                const float* __restrict__ conv_w,
                                                const float* __restrict__ conv_b)
{
    extern __shared__ __align__(16) float sb[];
    const int ntile = blockIdx.x;
    const int b     = blockIdx.y;
    const int n0    = ntile * NT1;
    const int tid   = threadIdx.x;
    const int ng    = tid & 31;
    const int tg    = tid >> 5;
    const unsigned sbase = smem_u32(sb);

    float* wd0 = sb;
    float* wd1 = sb + 4608;
    float* xs0 = sb + 9216;
    float* xs1 = sb + 17408;

    {   // prefetch chunk 0
        const float* xsrc = x + (size_t)b * CDIM * NDIM + n0;
        #pragma unroll
        for (int r = 0; r < 8; r++) {
            int i = tid + 256 * r, cc = i >> 6, q = i & 63;
            cpa16(sbase + (9216 + cc * 256 + 4 * q) * 4, xsrc + (size_t)cc * NDIM + 4 * q);
        }
        CP_COMMIT();
        for (int i = tid; i < 576; i += 256) {
            int t = i >> 3, q = i & 7;
            float4 v = *(const float4*)(conv_w + t * CDIM + 4 * q);
            float2* d = (float2*)&wd0[(t * 32 + 4 * q) * 2];
            d[0] = make_float2(v.x, v.x); d[1] = make_float2(v.y, v.y);
            d[2] = make_float2(v.z, v.z); d[3] = make_float2(v.w, v.w);
        }
    }

    ull acc[9][4];
    #pragma unroll
    for (int i = 0; i < 9; i++)
        #pragma unroll
        for (int j = 0; j < 4; j++) acc[i][j] = 0ull;
    ull ssq[4] = {0ull, 0ull, 0ull, 0ull};

    int p = 0;
    for (int ch = 0; ch < 16; ch++) {
        CP_WAIT0();
        __syncthreads();
        if (ch < 15) {
            const int c0n = (ch + 1) * 32;
            const float* xsrc = x + ((size_t)b * CDIM + c0n) * NDIM + n0;
            const unsigned xdst = sbase + (9216 + (1 - p) * 8192) * 4;
            #pragma unroll
            for (int r = 0; r < 8; r++) {
                int i = tid + 256 * r, cc = i >> 6, q = i & 63;
                cpa16(xdst + (cc * 256 + 4 * q) * 4, xsrc + (size_t)cc * NDIM + 4 * q);
            }
        }
        CP_COMMIT();
        if (ch < 15) {
            const int c0n = (ch + 1) * 32;
            float* wdn = (p == 0) ? wd1 : wd0;
            for (int i = tid; i < 576; i += 256) {
                int t = i >> 3, q = i & 7;
                float4 v = *(const float4*)(conv_w + t * CDIM + c0n + 4 * q);
                float2* d = (float2*)&wdn[(t * 32 + 4 * q) * 2];
                d[0] = make_float2(v.x, v.x); d[1] = make_float2(v.y, v.y);
                d[2] = make_float2(v.z, v.z); d[3] = make_float2(v.w, v.w);
            }
        }
        const float* xb = (p == 0) ? xs0 : xs1;
        const float* wb = (p == 0) ? wd0 : wd1;
        const bool do_ssq = (tg == (ch & 7));   // round-robin ssq across warps
        #pragma unroll 4
        for (int cc = 0; cc < 32; cc++) {
            ull xv[4];
            #pragma unroll
            for (int j = 0; j < 4; j++)
                xv[j] = *(const ull*)&xb[cc * 256 + 2 * ng + 64 * j];
            if (do_ssq) {
                #pragma unroll
                for (int j = 0; j < 4; j++) fma2(ssq[j], xv[j], xv[j]);
            }
            #pragma unroll
            for (int i = 0; i < 9; i++) {
                ull wp = *(const ull*)&wb[((tg * 9 + i) * 32 + cc) * 2];
                #pragma unroll
                for (int j = 0; j < 4; j++) fma2(acc[i][j], wp, xv[j]);
            }
        }
        p ^= 1;
    }
    __syncthreads();

    float* lg     = sb;            // [72][260]
    float* invn_s = sb + 18720;    // [256]
    float* ssq_s  = sb + 20000;    // [8][256]
    #pragma unroll
    for (int j = 0; j < 4; j++)
        *(ull*)&ssq_s[tg * 256 + 2 * ng + 64 * j] = ssq[j];
    __syncthreads();
    {
        float s = 0.0f;
        #pragma unroll
        for (int w = 0; w < 8; w++) s += ssq_s[w * 256 + tid];
        invn_s[tid] = 1.0f / fmaxf(sqrtf(s), 1e-12f);
    }
    __syncthreads();
    {
        ull inv[4];
        #pragma unroll
        for (int j = 0; j < 4; j++) inv[j] = *(const ull*)&invn_s[2 * ng + 64 * j];
        #pragma unroll
        for (int i = 0; i < 9; i++) {
            int t = tg * 9 + i;
            ull bd = dup2(conv_b[t]);
            #pragma unroll
            for (int j = 0; j < 4; j++) {
                ull l = bd;
                fma2(l, acc[i][j], inv[j]);
                *(ull*)&lg[t * 260 + 2 * ng + 64 * j] = l;
            }
        }
    }
    __syncthreads();

    {   // softmax over t, one thread per n
        const int n = tid;
        float mx = -1e30f;
        #pragma unroll 8
        for (int t = 0; t < TCL; t++) mx = fmaxf(mx, lg[t * 260 + n]);
        float s = 0.0f;
        #pragma unroll 8
        for (int t = 0; t < TCL; t++) {
            float e = __expf(lg[t * 260 + n] - mx);
            lg[t * 260 + n] = e;
            s += e;
        }
        float inv_s = 1.0f / s;
        float a2s   = inv_s * invn_s[n];
        __nv_bfloat16* gph = &g_a2h[(size_t)b * KCL * NDIM + n0 + n];
        __nv_bfloat16* gpl = &g_a2l[(size_t)b * KCL * NDIM + n0 + n];
        #pragma unroll 8
        for (int t = 0; t < TCL; t++) {
            float e = lg[t * 260 + n];
            if (t < KCL) {
                float v = e * a2s;
                __nv_bfloat16 h = __float2bfloat16(v);
                gph[(size_t)t * NDIM] = h;
                gpl[(size_t)t * NDIM] = __float2bfloat16(v - __bfloat162float(h));
            }
            lg[t * 260 + n] = e * inv_s;
        }
    }
    __syncthreads();
    if (tid < TCL) {
        float m = 0.0f;
        #pragma unroll 8
        for (int n = 0; n < NT1; n++) m += lg[tid * 260 + n];
        g_massp[((size_t)b * NTILES + ntile) * TCL + tid] = m;
    }
}

// ---------------------------------------------------------------------------
// Pass 2: HMMA (mma.sync bf16, 3-term hi/lo split).
// D[c,k] = sum_n x[c,n]*a2[k,n]; M=128(c) N=64(k) K=4096(n), chunks of 64 n.
// 8 warps 4x2 -> warp tile 32x32. Double-buffered smem (2 x 48KB), SW128.
// Both operands K-major in smem -> ldmatrix NON-trans for A and B.
// ---------------------------------------------------------------------------
#define A_H 0u
#define A_L 16384u
#define B_H 32768u
#define B_L 40960u
#define BUFSTRIDE 49152u

__global__ __launch_bounds__(256, 1) void pass2(const float* __restrict__ x)
{
    extern __shared__ char smem[];
    const unsigned sbase = smem_u32(smem);
    const int ct   = blockIdx.x;
    const int b    = blockIdx.y;
    const int c0   = ct * 128;
    const int tid  = threadIdx.x;
    const int lane = tid & 31;
    const int wid  = tid >> 5;
    const int warp_m = (wid & 3) * 32;
    const int warp_n = (wid >> 2) * 32;

    // gmem load geometry
    const int xrow = tid >> 4;          // 0..15; rows xrow+16r
    const int xq   = tid & 15;          // 4-float group in 64-n chunk
    const float* xbase = x + ((size_t)b * CDIM + c0 + xrow) * NDIM + 4 * xq;
    const int bk0 = tid >> 3;           // 0..31; rows bk0, bk0+32
    const int bq  = tid & 7;            // 8-bf16 group
    const __nv_bfloat16* bh0 = g_a2h + ((size_t)b * KCL + bk0) * NDIM + 8 * bq;
    const __nv_bfloat16* bh1 = bh0 + (size_t)32 * NDIM;
    const __nv_bfloat16* bl0 = g_a2l + ((size_t)b * KCL + bk0) * NDIM + 8 * bq;
    const __nv_bfloat16* bl1 = bl0 + (size_t)32 * NDIM;

    float acc[2][4][4];
    #pragma unroll
    for (int i = 0; i < 2; i++)
        #pragma unroll
        for (int j = 0; j < 4; j++)
            #pragma unroll
            for (int q = 0; q < 4; q++) acc[i][j][q] = 0.0f;

    float4 xr[2][8];
    uint4  bhr[2][2], blr[2][2];

#define P2_LOAD(S, CH) do {                                                          \
        const float* _xp = xbase + (CH) * 64;                                        \
        _Pragma("unroll")                                                            \
        for (int r = 0; r < 8; r++)                                                  \
            xr[S][r] = *(const float4*)(_xp + (size_t)16 * r * NDIM);                \
        bhr[S][0] = *(const uint4*)(bh0 + (CH) * 64);                                \
        bhr[S][1] = *(const uint4*)(bh1 + (CH) * 64);                                \
        blr[S][0] = *(const uint4*)(bl0 + (CH) * 64);                                \
        blr[S][1] = *(const uint4*)(bl1 + (CH) * 64);                                \
    } while (0)

    P2_LOAD(0, 0);

    for (int ch = 0; ch < 64; ch++) {
        const int S = ch & 1;
        if (ch + 1 < 64) P2_LOAD(1 - S, ch + 1);

        const unsigned buf = sbase + (unsigned)S * BUFSTRIDE;
        // ---- store phase: convert x -> bf16 hi/lo; raw copy a2 hi/lo -------
        #pragma unroll
        for (int r = 0; r < 8; r++) {
            float4 v = xr[S][r];
            unsigned off = (unsigned)((xrow + 16 * r) * 128 + 8 * xq);
            unsigned so  = swz(off);
            __nv_bfloat162 h01 = __floats2bfloat162_rn(v.x, v.y);
            __nv_bfloat162 h23 = __floats2bfloat162_rn(v.z, v.w);
            float2 f01 = __bfloat1622float2(h01);
            float2 f23 = __bfloat1622float2(h23);
            __nv_bfloat162 l01 = __floats2bfloat162_rn(v.x - f01.x, v.y - f01.y);
            __nv_bfloat162 l23 = __floats2bfloat162_rn(v.z - f23.x, v.w - f23.y);
            asm volatile("st.shared.v2.b32 [%0], {%1,%2};"
                :: "r"(buf + A_H + so), "r"(*(unsigned*)&h01), "r"(*(unsigned*)&h23));
            asm volatile("st.shared.v2.b32 [%0], {%1,%2};"
                :: "r"(buf + A_L + so), "r"(*(unsigned*)&l01), "r"(*(unsigned*)&l23));
        }
        {
            unsigned o0 = (unsigned)(bk0 * 128 + 16 * bq);
            unsigned o1 = (unsigned)((bk0 + 32) * 128 + 16 * bq);
            unsigned s0 = swz(o0), s1 = swz(o1);
            uint4 t0 = bhr[S][0], t1 = bhr[S][1], t2 = blr[S][0], t3 = blr[S][1];
            asm volatile("st.shared.v4.b32 [%0], {%1,%2,%3,%4};"
                :: "r"(buf + B_H + s0), "r"(t0.x), "r"(t0.y), "r"(t0.z), "r"(t0.w));
            asm volatile("st.shared.v4.b32 [%0], {%1,%2,%3,%4};"
                :: "r"(buf + B_H + s1), "r"(t1.x), "r"(t1.y), "r"(t1.z), "r"(t1.w));
            asm volatile("st.shared.v4.b32 [%0], {%1,%2,%3,%4};"
                :: "r"(buf + B_L + s0), "r"(t2.x), "r"(t2.y), "r"(t2.z), "r"(t2.w));
            asm volatile("st.shared.v4.b32 [%0], {%1,%2,%3,%4};"
                :: "r"(buf + B_L + s1), "r"(t3.x), "r"(t3.y), "r"(t3.z), "r"(t3.w));
        }
        __syncthreads();

        // ---- compute phase --------------------------------------------------
        #pragma unroll
        for (int ks = 0; ks < 4; ks++) {
            uint32_t ah[2][4], al[2][4], bh[2][4], bl[2][4];
            #pragma unroll
            for (int mf = 0; mf < 2; mf++) {
                unsigned off = (unsigned)((warp_m + mf * 16 + (lane & 15)) * 128
                                          + ks * 32 + (lane >> 4) * 16);
                unsigned so = swz(off);
                ldsm_x4(ah[mf], buf + A_H + so);
                ldsm_x4(al[mf], buf + A_L + so);
            }
            #pragma unroll
            for (int np = 0; np < 2; np++) {
                unsigned off = (unsigned)((warp_n + np * 16 + (lane >> 4) * 8 + (lane & 7)) * 128
                                          + ks * 32 + ((lane >> 3) & 1) * 16);
                unsigned so = swz(off);
                ldsm_x4(bh[np], buf + B_H + so);   // K-major B: NON-trans
                ldsm_x4(bl[np], buf + B_L + so);
            }
            #pragma unroll
            for (int mf = 0; mf < 2; mf++)
                #pragma unroll
                for (int np = 0; np < 2; np++)
                    #pragma unroll
                    for (int h = 0; h < 2; h++) {
                        float* c = acc[mf][np * 2 + h];
                        mma_bf16(c, ah[mf], &bh[np][2 * h]);
                        mma_bf16(c, ah[mf], &bl[np][2 * h]);
                        mma_bf16(c, al[mf], &bh[np][2 * h]);
                    }
        }
    }

    // ---- epilogue: acc -> g_agg[b][k][c] ------------------------------------
    const int bbase = b * KCL;
    #pragma unroll
    for (int mf = 0; mf < 2; mf++) {
        int row = c0 + warp_m + mf * 16 + (lane >> 2);
        #pragma unroll
        for (int nf = 0; nf < 4; nf++) {
            int k = warp_n + nf * 8 + (lane & 3) * 2;
            float* g0 = g_agg + (size_t)(bbase + k) * CDIM + row;
            g0[0]        = acc[mf][nf][0];
            g0[CDIM]     = acc[mf][nf][1];
            g0[8]        = acc[mf][nf][2];
            g0[CDIM + 8] = acc[mf][nf][3];
        }
    }
#undef P2_LOAD
}

// ---------------------------------------------------------------------------
// Pass 3: v = agg - centroid*mass; out = v/(max(||v||,eps)*8)
// (attention, ghost weighting and global norm cancel algebraically)
// ---------------------------------------------------------------------------
__global__ __launch_bounds__(128) void pass3(const float* __restrict__ centroids,
                                             float* __restrict__ out)
{
    const int k   = blockIdx.x;
    const int b   = blockIdx.y;
    const int tid = threadIdx.x;

    __shared__ float s_mass;
    __shared__ float s_red[4];

    if (tid == 0) {
        float m = 0.0f;
        #pragma unroll
        for (int t = 0; t < NTILES; t++) m += g_massp[((size_t)b * NTILES + t) * TCL + k];
        s_mass = m;
    }
    __syncthreads();
    const float mass = s_mass;

    float v[4];
    float ssq = 0.0f;
    #pragma unroll
    for (int j = 0; j < 4; j++) {
        int c = tid + 128 * j;
        float val = g_agg[((size_t)b * KCL + k) * CDIM + c] - centroids[k * CDIM + c] * mass;
        v[j] = val;
        ssq = fmaf(val, val, ssq);
    }
    #pragma unroll
    for (int o = 16; o > 0; o >>= 1) ssq += __shfl_xor_sync(0xffffffffu, ssq, o);
    if ((tid & 31) == 0) s_red[tid >> 5] = ssq;
    __syncthreads();
    float tot = s_red[0] + s_red[1] + s_red[2] + s_red[3];
    float scale = 1.0f / (fmaxf(sqrtf(tot), 1e-12f) * 8.0f);
    #pragma unroll
    for (int j = 0; j < 4; j++)
        out[((size_t)b * KCL + k) * CDIM + tid + 128 * j] = v[j] * scale;
}

// ---------------------------------------------------------------------------
extern "C" void kernel_launch(void* const* d_in, const int* in_sizes, int n_in,
                              void* d_out, int out_size)
{
    const float* x         = (const float*)d_in[0];
    const float* centroids = (const float*)d_in[1];
    const float* conv_w    = (const float*)d_in[2];
    const float* conv_b    = (const float*)d_in[3];
    float* out = (float*)d_out;

    cudaFuncSetAttribute(pass1, cudaFuncAttributeMaxDynamicSharedMemorySize, 102400);
    cudaFuncSetAttribute(pass2, cudaFuncAttributeMaxDynamicSharedMemorySize, 98304);

    pass1<<<dim3(NTILES, BATCH), 256, 102400>>>(x, conv_w, conv_b);
    pass2<<<dim3(4, BATCH), 256, 98304>>>(x);
    pass3<<<dim3(KCL, BATCH), 128>>>(centroids, out);
}

// round 7
// speedup vs baseline: 2.7496x; 1.3298x over previous
#include <cuda_runtime.h>
#include <cuda_bf16.h>
#include <math.h>
#include <stdint.h>

#define BATCH 32
#define CDIM  512
#define NDIM  4096
#define TCL   72
#define KCL   64
#define NT1   128
#define NTILES 32            // 4096/128

// Scratch (static device globals; no runtime allocation)
__device__ __nv_bfloat16 g_a2h[(size_t)BATCH * KCL * NDIM];
__device__ float g_massp[(size_t)BATCH * NTILES * KCL];
__device__ float g_agg[(size_t)BATCH * KCL * CDIM];

__device__ __forceinline__ unsigned smem_u32(const void* p) {
    unsigned a;
    asm("{ .reg .u64 t; cvta.to.shared.u64 t, %1; cvt.u32.u64 %0, t; }" : "=r"(a) : "l"(p));
    return a;
}
__device__ __forceinline__ void ldsm_x4(uint32_t* r, unsigned addr) {
    asm volatile("ldmatrix.sync.aligned.m8n8.x4.shared.b16 {%0,%1,%2,%3}, [%4];"
                 : "=r"(r[0]), "=r"(r[1]), "=r"(r[2]), "=r"(r[3]) : "r"(addr));
}
__device__ __forceinline__ void ldsm_x4t(uint32_t* r, unsigned addr) {
    asm volatile("ldmatrix.sync.aligned.m8n8.x4.trans.shared.b16 {%0,%1,%2,%3}, [%4];"
                 : "=r"(r[0]), "=r"(r[1]), "=r"(r[2]), "=r"(r[3]) : "r"(addr));
}
__device__ __forceinline__ void mma_bf16(float* c, const uint32_t* a, const uint32_t* b) {
    asm volatile(
        "mma.sync.aligned.m16n8k16.row.col.f32.bf16.bf16.f32 "
        "{%0,%1,%2,%3},{%4,%5,%6,%7},{%8,%9},{%0,%1,%2,%3};"
        : "+f"(c[0]), "+f"(c[1]), "+f"(c[2]), "+f"(c[3])
        : "r"(a[0]), "r"(a[1]), "r"(a[2]), "r"(a[3]), "r"(b[0]), "r"(b[1]));
}
__device__ __forceinline__ void sts_v2(unsigned addr, __nv_bfloat162 p0, __nv_bfloat162 p1) {
    asm volatile("st.shared.v2.b32 [%0], {%1,%2};"
                 :: "r"(addr), "r"(*(unsigned*)&p0), "r"(*(unsigned*)&p1));
}

// ---------------------------------------------------------------------------
// Pass 1 (HMMA): raw[n,t] = sum_c x[c,n] W[t,c]  (bf16 mma, fp32 accum)
// then logits = raw*invn + bias, softmax over t, a2 = assign*invn (bf16 out),
// mass partials. Block = 128 n (M) x 80 t-padded (N), K = 512 c in 8 chunks.
// 8 warps, each m16 x all t. A = x^T via ldmatrix.trans from [c][n] smem.
// ---------------------------------------------------------------------------
__global__ __launch_bounds__(256) void pass1(const float* __restrict__ x,
                                             const float* __restrict__ conv_w,
                                             const float* __restrict__ conv_b)
{
    extern __shared__ char sm[];
    const unsigned sb = smem_u32(sm);
    const int ntile = blockIdx.x;
    const int b     = blockIdx.y;
    const int n0    = ntile * NT1;
    const int tid   = threadIdx.x;
    const int lane  = tid & 31;
    const int wid   = tid >> 5;
    const int m0    = wid * 16;

    // smem byte offsets
    const unsigned XB0 = 0, XB1 = 16384, WB0 = 32768, WB1 = 43008;   // phase A
    const unsigned LG = 0, A2ST = 43008, SSQS = 59392, INVN = 63488, BIAS = 64000;

    if (tid < 80) {
        float v = (tid < TCL) ? conv_b[tid] : 0.0f;
        *(float*)(sm + BIAS + tid * 4) = v;
    }

    // x load geometry: warp wid covers c rows wid+8r; lane = n-group of 4
    const float* xsrc = x + (size_t)b * CDIM * NDIM + n0 + 4 * lane;
    float4 xr[2][8];
#define LD_X(S, CH) do {                                                       \
        const float* _p = xsrc + (size_t)((CH) * 64 + wid) * NDIM;             \
        _Pragma("unroll")                                                      \
        for (int r = 0; r < 8; r++) xr[S][r] = *(const float4*)(_p + (size_t)8 * r * NDIM); \
    } while (0)

    LD_X(0, 0);

    float acc[10][4];
    #pragma unroll
    for (int i = 0; i < 10; i++)
        #pragma unroll
        for (int j = 0; j < 4; j++) acc[i][j] = 0.0f;
    float ssq4[4] = {0.f, 0.f, 0.f, 0.f};

    for (int ch = 0; ch < 8; ch++) {
        const int S = ch & 1;
        if (ch < 7) LD_X(1 - S, ch + 1);
        const unsigned xb = sb + (S ? XB1 : XB0);
        const unsigned wb = sb + (S ? WB1 : WB0);

        // W chunk [80 t][64 c] bf16 (rows 72-79 zero), 128B rows swizzled
        #pragma unroll
        for (int it = 0; it < 5; it++) {
            int idx = tid + 256 * it;
            int t = idx >> 4, qq = idx & 15;
            float4 v = make_float4(0.f, 0.f, 0.f, 0.f);
            if (t < TCL) v = *(const float4*)(conv_w + t * CDIM + ch * 64 + 4 * qq);
            unsigned off = (unsigned)(t * 128 + 8 * qq);
            sts_v2(wb + (off ^ ((off >> 3) & 0x70)),
                   __floats2bfloat162_rn(v.x, v.y), __floats2bfloat162_rn(v.z, v.w));
        }
        // x chunk [64 c][128 n] bf16, 256B rows swizzled; fp32 ssq alongside
        #pragma unroll
        for (int r = 0; r < 8; r++) {
            float4 v = xr[S][r];
            ssq4[0] = fmaf(v.x, v.x, ssq4[0]);
            ssq4[1] = fmaf(v.y, v.y, ssq4[1]);
            ssq4[2] = fmaf(v.z, v.z, ssq4[2]);
            ssq4[3] = fmaf(v.w, v.w, ssq4[3]);
            unsigned off = (unsigned)((wid + 8 * r) * 256 + 8 * lane);
            sts_v2(xb + (off ^ ((off >> 4) & 0x70)),
                   __floats2bfloat162_rn(v.x, v.y), __floats2bfloat162_rn(v.z, v.w));
        }
        __syncthreads();

        #pragma unroll
        for (int ks = 0; ks < 4; ks++) {
            uint32_t a[4];
            {   // A^T load: stored [c][n]; trans gives row-major n x c fragments
                int crow = ks * 16 + (lane & 7) + ((lane >> 4) & 1) * 8;
                int ncol = m0 + ((lane >> 3) & 1) * 8;
                unsigned off = (unsigned)(crow * 256 + ncol * 2);
                ldsm_x4t(a, xb + (off ^ ((off >> 4) & 0x70)));
            }
            #pragma unroll
            for (int nb = 0; nb < 5; nb++) {
                uint32_t bf[4];
                int trow = nb * 16 + ((lane >> 4) & 1) * 8 + (lane & 7);
                unsigned off = (unsigned)(trow * 128 + ks * 32 + ((lane >> 3) & 1) * 16);
                ldsm_x4(bf, wb + (off ^ ((off >> 3) & 0x70)));
                mma_bf16(acc[2 * nb],     a, &bf[0]);
                mma_bf16(acc[2 * nb + 1], a, &bf[2]);
            }
        }
    }
    __syncthreads();

    // ssq reduce -> invn
    *(float4*)(sm + SSQS + (wid * 32 + lane) * 16) = *(float4*)ssq4;
    __syncthreads();
    if (tid < 128) {
        const float* fs = (const float*)(sm + SSQS);
        float s = 0.0f;
        #pragma unroll
        for (int w2 = 0; w2 < 8; w2++) s += fs[w2 * 128 + tid];
        ((float*)(sm + INVN))[tid] = 1.0f / fmaxf(sqrtf(s), 1e-12f);
    }
    __syncthreads();

    // fragments -> logits smem [128 n][84 t]
    {
        float* lg = (float*)(sm + LG);
        const float* invn = (const float*)(sm + INVN);
        const float* bias = (const float*)(sm + BIAS);
        int r0 = m0 + (lane >> 2);
        float i0 = invn[r0], i1 = invn[r0 + 8];
        #pragma unroll
        for (int nb = 0; nb < 10; nb++) {
            int tc = nb * 8 + 2 * (lane & 3);
            float b0 = bias[tc], b1 = bias[tc + 1];
            lg[r0 * 84 + tc]           = acc[nb][0] * i0 + b0;
            lg[r0 * 84 + tc + 1]       = acc[nb][1] * i0 + b1;
            lg[(r0 + 8) * 84 + tc]     = acc[nb][2] * i1 + b0;
            lg[(r0 + 8) * 84 + tc + 1] = acc[nb][3] * i1 + b1;
        }
    }
    __syncthreads();

    // softmax per n; a2 (bf16) into staging; assign back into lg
    if (tid < 128) {
        float* row = (float*)(sm + LG) + tid * 84;
        float invn_n = ((float*)(sm + INVN))[tid];
        float mx = -1e30f;
        #pragma unroll 8
        for (int t = 0; t < TCL; t++) mx = fmaxf(mx, row[t]);
        float s = 0.0f;
        #pragma unroll 8
        for (int t = 0; t < TCL; t++) { float e = __expf(row[t] - mx); row[t] = e; s += e; }
        float inv_s = 1.0f / s;
        float a2s   = inv_s * invn_n;
        __nv_bfloat16* a2st = (__nv_bfloat16*)(sm + A2ST);
        #pragma unroll 8
        for (int t = 0; t < TCL; t++) {
            float e = row[t];
            if (t < KCL) a2st[t * 128 + tid] = __float2bfloat16(e * a2s);
            row[t] = e * inv_s;
        }
    }
    __syncthreads();

    // coalesced a2 writeout: [64 k][128 n] bf16 = 16KB
    #pragma unroll
    for (int it = 0; it < 4; it++) {
        int idx = tid + 256 * it;
        int k = idx >> 4, qq = idx & 15;
        *(uint4*)((char*)(g_a2h + ((size_t)(b * KCL + k)) * NDIM + n0) + 16 * qq)
            = *(const uint4*)(sm + A2ST + k * 256 + 16 * qq);
    }
    // mass partials (k<64 only; ghosts never read downstream)
    if (tid < KCL) {
        const float* lg = (const float*)(sm + LG);
        float m = 0.0f;
        #pragma unroll 8
        for (int n = 0; n < NT1; n++) m += lg[n * 84 + tid];
        g_massp[((size_t)b * NTILES + ntile) * KCL + tid] = m;
    }
#undef LD_X
}

// ---------------------------------------------------------------------------
// Pass 2: HMMA single-bf16. D[c,k] = sum_n x[c,n]*a2[k,n]
// M=128(c) N=64(k) K=4096(n), chunks of 64 n. 8 warps 4x2, warp tile 32x32.
// Double-buffered smem (2 x 24KB), SW128. K-major both -> non-trans ldmatrix.
// ---------------------------------------------------------------------------
#define A_H 0u
#define B_H 16384u
#define BUFSTRIDE 24576u

__global__ __launch_bounds__(256) void pass2(const float* __restrict__ x)
{
    extern __shared__ char smem[];
    const unsigned sbase = smem_u32(smem);
    const int ct   = blockIdx.x;
    const int b    = blockIdx.y;
    const int c0   = ct * 128;
    const int tid  = threadIdx.x;
    const int lane = tid & 31;
    const int wid  = tid >> 5;
    const int warp_m = (wid & 3) * 32;
    const int warp_n = (wid >> 2) * 32;

    const int xrow = tid >> 4;
    const int xq   = tid & 15;
    const float* xbase = x + ((size_t)b * CDIM + c0 + xrow) * NDIM + 4 * xq;
    const int bk0 = tid >> 3;
    const int bq  = tid & 7;
    const __nv_bfloat16* bh0 = g_a2h + ((size_t)b * KCL + bk0) * NDIM + 8 * bq;
    const __nv_bfloat16* bh1 = bh0 + (size_t)32 * NDIM;

    float acc[2][4][4];
    #pragma unroll
    for (int i = 0; i < 2; i++)
        #pragma unroll
        for (int j = 0; j < 4; j++)
            #pragma unroll
            for (int q = 0; q < 4; q++) acc[i][j][q] = 0.0f;

    float4 xr[2][8];
    uint4  bhr[2][2];

#define P2_LOAD(S, CH) do {                                                    \
        const float* _xp = xbase + (CH) * 64;                                  \
        _Pragma("unroll")                                                      \
        for (int r = 0; r < 8; r++)                                            \
            xr[S][r] = *(const float4*)(_xp + (size_t)16 * r * NDIM);          \
        bhr[S][0] = *(const uint4*)(bh0 + (CH) * 64);                          \
        bhr[S][1] = *(const uint4*)(bh1 + (CH) * 64);                          \
    } while (0)

    P2_LOAD(0, 0);

    for (int ch = 0; ch < 64; ch++) {
        const int S = ch & 1;
        if (ch + 1 < 64) P2_LOAD(1 - S, ch + 1);

        const unsigned buf = sbase + (unsigned)S * BUFSTRIDE;
        #pragma unroll
        for (int r = 0; r < 8; r++) {
            float4 v = xr[S][r];
            unsigned off = (unsigned)((xrow + 16 * r) * 128 + 8 * xq);
            unsigned so  = off ^ ((off >> 3) & 0x70);
            sts_v2(buf + A_H + so,
                   __floats2bfloat162_rn(v.x, v.y), __floats2bfloat162_rn(v.z, v.w));
        }
        {
            unsigned o0 = (unsigned)(bk0 * 128 + 16 * bq);
            unsigned o1 = (unsigned)((bk0 + 32) * 128 + 16 * bq);
            unsigned s0 = o0 ^ ((o0 >> 3) & 0x70);
            unsigned s1 = o1 ^ ((o1 >> 3) & 0x70);
            uint4 t0 = bhr[S][0], t1 = bhr[S][1];
            asm volatile("st.shared.v4.b32 [%0], {%1,%2,%3,%4};"
                :: "r"(buf + B_H + s0), "r"(t0.x), "r"(t0.y), "r"(t0.z), "r"(t0.w));
            asm volatile("st.shared.v4.b32 [%0], {%1,%2,%3,%4};"
                :: "r"(buf + B_H + s1), "r"(t1.x), "r"(t1.y), "r"(t1.z), "r"(t1.w));
        }
        __syncthreads();

        #pragma unroll
        for (int ks = 0; ks < 4; ks++) {
            uint32_t ah[2][4], bh2[2][4];
            #pragma unroll
            for (int mf = 0; mf < 2; mf++) {
                unsigned off = (unsigned)((warp_m + mf * 16 + (lane & 15)) * 128
                                          + ks * 32 + (lane >> 4) * 16);
                ldsm_x4(ah[mf], buf + A_H + (off ^ ((off >> 3) & 0x70)));
            }
            #pragma unroll
            for (int np = 0; np < 2; np++) {
                unsigned off = (unsigned)((warp_n + np * 16 + (lane >> 4) * 8 + (lane & 7)) * 128
                                          + ks * 32 + ((lane >> 3) & 1) * 16);
                ldsm_x4(bh2[np], buf + B_H + (off ^ ((off >> 3) & 0x70)));
            }
            #pragma unroll
            for (int mf = 0; mf < 2; mf++)
                #pragma unroll
                for (int np = 0; np < 2; np++)
                    #pragma unroll
                    for (int h = 0; h < 2; h++)
                        mma_bf16(acc[mf][np * 2 + h], ah[mf], &bh2[np][2 * h]);
        }
    }

    const int bbase = b * KCL;
    #pragma unroll
    for (int mf = 0; mf < 2; mf++) {
        int row = c0 + warp_m + mf * 16 + (lane >> 2);
        #pragma unroll
        for (int nf = 0; nf < 4; nf++) {
            int k = warp_n + nf * 8 + (lane & 3) * 2;
            float* g0 = g_agg + (size_t)(bbase + k) * CDIM + row;
            g0[0]        = acc[mf][nf][0];
            g0[CDIM]     = acc[mf][nf][1];
            g0[8]        = acc[mf][nf][2];
            g0[CDIM + 8] = acc[mf][nf][3];
        }
    }
#undef P2_LOAD
}

// ---------------------------------------------------------------------------
// Pass 3: v = agg - centroid*mass; out = v/(max(||v||,eps)*8)
// (attention, ghost weighting and global norm cancel algebraically)
// ---------------------------------------------------------------------------
__global__ __launch_bounds__(128) void pass3(const float* __restrict__ centroids,
                                             float* __restrict__ out)
{
    const int k   = blockIdx.x;
    const int b   = blockIdx.y;
    const int tid = threadIdx.x;

    __shared__ float s_mass;
    __shared__ float s_red[4];

    if (tid == 0) {
        float m = 0.0f;
        #pragma unroll
        for (int t = 0; t < NTILES; t++) m += g_massp[((size_t)b * NTILES + t) * KCL + k];
        s_mass = m;
    }
    __syncthreads();
    const float mass = s_mass;

    float v[4];
    float ssq = 0.0f;
    #pragma unroll
    for (int j = 0; j < 4; j++) {
        int c = tid + 128 * j;
        float val = g_agg[((size_t)b * KCL + k) * CDIM + c] - centroids[k * CDIM + c] * mass;
        v[j] = val;
        ssq = fmaf(val, val, ssq);
    }
    #pragma unroll
    for (int o = 16; o > 0; o >>= 1) ssq += __shfl_xor_sync(0xffffffffu, ssq, o);
    if ((tid & 31) == 0) s_red[tid >> 5] = ssq;
    __syncthreads();
    float tot = s_red[0] + s_red[1] + s_red[2] + s_red[3];
    float scale = 1.0f / (fmaxf(sqrtf(tot), 1e-12f) * 8.0f);
    #pragma unroll
    for (int j = 0; j < 4; j++)
        out[((size_t)b * KCL + k) * CDIM + tid + 128 * j] = v[j] * scale;
}

// ---------------------------------------------------------------------------
extern "C" void kernel_launch(void* const* d_in, const int* in_sizes, int n_in,
                              void* d_out, int out_size)
{
    const float* x         = (const float*)d_in[0];
    const float* centroids = (const float*)d_in[1];
    const float* conv_w    = (const float*)d_in[2];
    const float* conv_b    = (const float*)d_in[3];
    float* out = (float*)d_out;

    cudaFuncSetAttribute(pass1, cudaFuncAttributeMaxDynamicSharedMemorySize, 64512);
    cudaFuncSetAttribute(pass2, cudaFuncAttributeMaxDynamicSharedMemorySize, 49152);

    pass1<<<dim3(NTILES, BATCH), 256, 64512>>>(x, conv_w, conv_b);
    pass2<<<dim3(4, BATCH), 256, 49152>>>(x);
    pass3<<<dim3(KCL, BATCH), 128>>>(centroids, out);
}

// round 8
// speedup vs baseline: 4.4355x; 1.6132x over previous
#include <cuda_runtime.h>
#include <cuda_bf16.h>
#include <math.h>
#include <stdint.h>

#define BATCH 32
#define CDIM  512
#define NDIM  4096
#define TCL   72
#define KCL   64
#define NT1   128
#define NTILES 32            // 4096/128

// Scratch (static device globals; no runtime allocation)
__device__ __nv_bfloat16 g_a2h[(size_t)BATCH * KCL * NDIM];   // assign*invn, bf16
__device__ __nv_bfloat16 g_xb[(size_t)BATCH * CDIM * NDIM];   // x in bf16 (pass1 byproduct)
__device__ float g_massp[(size_t)BATCH * NTILES * KCL];
__device__ float g_agg[(size_t)BATCH * KCL * CDIM];

__device__ __forceinline__ unsigned smem_u32(const void* p) {
    unsigned a;
    asm("{ .reg .u64 t; cvta.to.shared.u64 t, %1; cvt.u32.u64 %0, t; }" : "=r"(a) : "l"(p));
    return a;
}
__device__ __forceinline__ void ldsm_x4(uint32_t* r, unsigned addr) {
    asm volatile("ldmatrix.sync.aligned.m8n8.x4.shared.b16 {%0,%1,%2,%3}, [%4];"
                 : "=r"(r[0]), "=r"(r[1]), "=r"(r[2]), "=r"(r[3]) : "r"(addr));
}
__device__ __forceinline__ void ldsm_x4t(uint32_t* r, unsigned addr) {
    asm volatile("ldmatrix.sync.aligned.m8n8.x4.trans.shared.b16 {%0,%1,%2,%3}, [%4];"
                 : "=r"(r[0]), "=r"(r[1]), "=r"(r[2]), "=r"(r[3]) : "r"(addr));
}
__device__ __forceinline__ void mma_bf16(float* c, const uint32_t* a, const uint32_t* b) {
    asm volatile(
        "mma.sync.aligned.m16n8k16.row.col.f32.bf16.bf16.f32 "
        "{%0,%1,%2,%3},{%4,%5,%6,%7},{%8,%9},{%0,%1,%2,%3};"
        : "+f"(c[0]), "+f"(c[1]), "+f"(c[2]), "+f"(c[3])
        : "r"(a[0]), "r"(a[1]), "r"(a[2]), "r"(a[3]), "r"(b[0]), "r"(b[1]));
}
__device__ __forceinline__ void sts_v2(unsigned addr, __nv_bfloat162 p0, __nv_bfloat162 p1) {
    asm volatile("st.shared.v2.b32 [%0], {%1,%2};"
                 :: "r"(addr), "r"(*(unsigned*)&p0), "r"(*(unsigned*)&p1));
}
__device__ __forceinline__ void cpa16(unsigned dst, const void* src) {
    asm volatile("cp.async.cg.shared.global [%0], [%1], 16;" :: "r"(dst), "l"(src));
}
#define CP_COMMIT() asm volatile("cp.async.commit_group;")

// ---------------------------------------------------------------------------
// Pass 1 (HMMA): raw[n,t] = sum_c x[c,n] W[t,c]; logits = raw*invn + bias;
// softmax over t; a2 = assign*invn (bf16); mass partials; and x->bf16 (g_xb).
// Block = 128 n x 80 t (padded), K = 512 c in 8 chunks of 64.
// ---------------------------------------------------------------------------
__global__ __launch_bounds__(256) void pass1(const float* __restrict__ x,
                                             const float* __restrict__ conv_w,
                                             const float* __restrict__ conv_b)
{
    extern __shared__ char sm[];
    const unsigned sb = smem_u32(sm);
    const int ntile = blockIdx.x;
    const int b     = blockIdx.y;
    const int n0    = ntile * NT1;
    const int tid   = threadIdx.x;
    const int lane  = tid & 31;
    const int wid   = tid >> 5;
    const int m0    = wid * 16;

    // smem byte offsets
    const unsigned XB0 = 0, XB1 = 16384, WB0 = 32768, WB1 = 43008;   // phase A
    const unsigned LG = 0, A2ST = 43008, SSQS = 59392, INVN = 63488, BIAS = 64000;

    if (tid < 80) {
        float v = (tid < TCL) ? conv_b[tid] : 0.0f;
        *(float*)(sm + BIAS + tid * 4) = v;
    }

    const float* xsrc = x + (size_t)b * CDIM * NDIM + n0 + 4 * lane;
    __nv_bfloat16* xbout = g_xb + (size_t)b * CDIM * NDIM + n0 + 4 * lane;
    float4 xr[2][8];
#define LD_X(S, CH) do {                                                       \
        const float* _p = xsrc + (size_t)((CH) * 64 + wid) * NDIM;             \
        _Pragma("unroll")                                                      \
        for (int r = 0; r < 8; r++) xr[S][r] = *(const float4*)(_p + (size_t)8 * r * NDIM); \
    } while (0)

    LD_X(0, 0);

    float acc[10][4];
    #pragma unroll
    for (int i = 0; i < 10; i++)
        #pragma unroll
        for (int j = 0; j < 4; j++) acc[i][j] = 0.0f;
    float ssq4[4] = {0.f, 0.f, 0.f, 0.f};

    for (int ch = 0; ch < 8; ch++) {
        const int S = ch & 1;
        if (ch < 7) LD_X(1 - S, ch + 1);
        const unsigned xb = sb + (S ? XB1 : XB0);
        const unsigned wb = sb + (S ? WB1 : WB0);

        // W chunk [80 t][64 c] bf16 (rows 72-79 zero), 128B rows swizzled
        #pragma unroll
        for (int it = 0; it < 5; it++) {
            int idx = tid + 256 * it;
            int t = idx >> 4, qq = idx & 15;
            float4 v = make_float4(0.f, 0.f, 0.f, 0.f);
            if (t < TCL) v = *(const float4*)(conv_w + t * CDIM + ch * 64 + 4 * qq);
            unsigned off = (unsigned)(t * 128 + 8 * qq);
            sts_v2(wb + (off ^ ((off >> 3) & 0x70)),
                   __floats2bfloat162_rn(v.x, v.y), __floats2bfloat162_rn(v.z, v.w));
        }
        // x chunk [64 c][128 n] bf16, 256B rows swizzled; ssq + g_xb writeout
        #pragma unroll
        for (int r = 0; r < 8; r++) {
            float4 v = xr[S][r];
            ssq4[0] = fmaf(v.x, v.x, ssq4[0]);
            ssq4[1] = fmaf(v.y, v.y, ssq4[1]);
            ssq4[2] = fmaf(v.z, v.z, ssq4[2]);
            ssq4[3] = fmaf(v.w, v.w, ssq4[3]);
            __nv_bfloat162 h01 = __floats2bfloat162_rn(v.x, v.y);
            __nv_bfloat162 h23 = __floats2bfloat162_rn(v.z, v.w);
            unsigned off = (unsigned)((wid + 8 * r) * 256 + 8 * lane);
            sts_v2(xb + (off ^ ((off >> 4) & 0x70)), h01, h23);
            uint2 u; u.x = *(unsigned*)&h01; u.y = *(unsigned*)&h23;
            *(uint2*)(xbout + (size_t)(ch * 64 + wid + 8 * r) * NDIM) = u;
        }
        __syncthreads();

        #pragma unroll
        for (int ks = 0; ks < 4; ks++) {
            uint32_t a[4];
            {   // A^T load: stored [c][n]; trans gives row-major n x c fragments
                int crow = ks * 16 + (lane & 7) + ((lane >> 4) & 1) * 8;
                int ncol = m0 + ((lane >> 3) & 1) * 8;
                unsigned off = (unsigned)(crow * 256 + ncol * 2);
                ldsm_x4t(a, xb + (off ^ ((off >> 4) & 0x70)));
            }
            #pragma unroll
            for (int nb = 0; nb < 5; nb++) {
                uint32_t bf[4];
                int trow = nb * 16 + ((lane >> 4) & 1) * 8 + (lane & 7);
                unsigned off = (unsigned)(trow * 128 + ks * 32 + ((lane >> 3) & 1) * 16);
                ldsm_x4(bf, wb + (off ^ ((off >> 3) & 0x70)));
                mma_bf16(acc[2 * nb],     a, &bf[0]);
                mma_bf16(acc[2 * nb + 1], a, &bf[2]);
            }
        }
    }
    __syncthreads();

    // ssq reduce -> invn
    *(float4*)(sm + SSQS + (wid * 32 + lane) * 16) = *(float4*)ssq4;
    __syncthreads();
    if (tid < 128) {
        const float* fs = (const float*)(sm + SSQS);
        float s = 0.0f;
        #pragma unroll
        for (int w2 = 0; w2 < 8; w2++) s += fs[w2 * 128 + tid];
        ((float*)(sm + INVN))[tid] = 1.0f / fmaxf(sqrtf(s), 1e-12f);
    }
    __syncthreads();

    // fragments -> logits smem [128 n][84 t]
    {
        float* lg = (float*)(sm + LG);
        const float* invn = (const float*)(sm + INVN);
        const float* bias = (const float*)(sm + BIAS);
        int r0 = m0 + (lane >> 2);
        float i0 = invn[r0], i1 = invn[r0 + 8];
        #pragma unroll
        for (int nb = 0; nb < 10; nb++) {
            int tc = nb * 8 + 2 * (lane & 3);
            float b0 = bias[tc], b1 = bias[tc + 1];
            lg[r0 * 84 + tc]           = acc[nb][0] * i0 + b0;
            lg[r0 * 84 + tc + 1]       = acc[nb][1] * i0 + b1;
            lg[(r0 + 8) * 84 + tc]     = acc[nb][2] * i1 + b0;
            lg[(r0 + 8) * 84 + tc + 1] = acc[nb][3] * i1 + b1;
        }
    }
    __syncthreads();

    // softmax per n; a2 (bf16) into staging; assign back into lg
    if (tid < 128) {
        float* row = (float*)(sm + LG) + tid * 84;
        float invn_n = ((float*)(sm + INVN))[tid];
        float mx = -1e30f;
        #pragma unroll 8
        for (int t = 0; t < TCL; t++) mx = fmaxf(mx, row[t]);
        float s = 0.0f;
        #pragma unroll 8
        for (int t = 0; t < TCL; t++) { float e = __expf(row[t] - mx); row[t] = e; s += e; }
        float inv_s = 1.0f / s;
        float a2s   = inv_s * invn_n;
        __nv_bfloat16* a2st = (__nv_bfloat16*)(sm + A2ST);
        #pragma unroll 8
        for (int t = 0; t < TCL; t++) {
            float e = row[t];
            if (t < KCL) a2st[t * 128 + tid] = __float2bfloat16(e * a2s);
            row[t] = e * inv_s;
        }
    }
    __syncthreads();

    // coalesced a2 writeout: [64 k][128 n] bf16 = 16KB
    #pragma unroll
    for (int it = 0; it < 4; it++) {
        int idx = tid + 256 * it;
        int k = idx >> 4, qq = idx & 15;
        *(uint4*)((char*)(g_a2h + ((size_t)(b * KCL + k)) * NDIM + n0) + 16 * qq)
            = *(const uint4*)(sm + A2ST + k * 256 + 16 * qq);
    }
    // mass partials (k<64 only; ghosts never read downstream)
    if (tid < KCL) {
        const float* lg = (const float*)(sm + LG);
        float m = 0.0f;
        #pragma unroll 8
        for (int n = 0; n < NT1; n++) m += lg[n * 84 + tid];
        g_massp[((size_t)b * NTILES + ntile) * KCL + tid] = m;
    }
#undef LD_X
}

// ---------------------------------------------------------------------------
// Pass 2: HMMA bf16, 4-stage cp.async pipeline, no conversions.
// D[c,k] = sum_n xb[c,n]*a2[k,n]; M=128(c) N=64(k) K=4096(n), 64-n chunks.
// Stage = 24KB: X [128c][64n] bf16 (128B rows, SW128) + A2 [64k][64n].
// 8 warps 4x2, warp tile 32x32.
// ---------------------------------------------------------------------------
#define STG_SZ 24576u
#define B_OFF  16384u

__global__ __launch_bounds__(256) void pass2()
{
    extern __shared__ char smem[];
    const unsigned sbase = smem_u32(smem);
    const int ct   = blockIdx.x;
    const int b    = blockIdx.y;
    const int c0   = ct * 128;
    const int tid  = threadIdx.x;
    const int lane = tid & 31;
    const int wid  = tid >> 5;
    const int warp_m = (wid & 3) * 32;
    const int warp_n = (wid >> 2) * 32;

    const __nv_bfloat16* xsrc = g_xb + ((size_t)b * CDIM + c0) * NDIM;
    const __nv_bfloat16* asrc = g_a2h + (size_t)b * KCL * NDIM;

#define P2_ISSUE(ST, CH) do {                                                  \
        unsigned _buf = sbase + (unsigned)(ST) * STG_SZ;                       \
        _Pragma("unroll")                                                      \
        for (int r = 0; r < 4; r++) {                                          \
            int g = tid + 256 * r; int row = g >> 3, c16 = g & 7;              \
            unsigned off = (unsigned)(row * 128 + c16 * 16);                   \
            cpa16(_buf + (off ^ ((off >> 3) & 0x70)),                          \
                  xsrc + (size_t)row * NDIM + (CH) * 64 + c16 * 8);            \
        }                                                                      \
        _Pragma("unroll")                                                      \
        for (int r = 0; r < 2; r++) {                                          \
            int g = tid + 256 * r; int k = g >> 3, c16 = g & 7;                \
            unsigned off = (unsigned)(k * 128 + c16 * 16);                     \
            cpa16(_buf + B_OFF + (off ^ ((off >> 3) & 0x70)),                  \
                  asrc + (size_t)k * NDIM + (CH) * 64 + c16 * 8);              \
        }                                                                      \
    } while (0)

    P2_ISSUE(0, 0); CP_COMMIT();
    P2_ISSUE(1, 1); CP_COMMIT();
    P2_ISSUE(2, 2); CP_COMMIT();

    float acc[2][4][4];
    #pragma unroll
    for (int i = 0; i < 2; i++)
        #pragma unroll
        for (int j = 0; j < 4; j++)
            #pragma unroll
            for (int q = 0; q < 4; q++) acc[i][j][q] = 0.0f;

    for (int ch = 0; ch < 64; ch++) {
        asm volatile("cp.async.wait_group 2;" ::: "memory");
        __syncthreads();
        if (ch + 3 < 64) P2_ISSUE((ch + 3) & 3, ch + 3);
        CP_COMMIT();

        const unsigned buf = sbase + (unsigned)(ch & 3) * STG_SZ;
        #pragma unroll
        for (int ks = 0; ks < 4; ks++) {
            uint32_t ah[2][4], bh2[2][4];
            #pragma unroll
            for (int mf = 0; mf < 2; mf++) {
                unsigned off = (unsigned)((warp_m + mf * 16 + (lane & 15)) * 128
                                          + ks * 32 + (lane >> 4) * 16);
                ldsm_x4(ah[mf], buf + (off ^ ((off >> 3) & 0x70)));
            }
            #pragma unroll
            for (int np = 0; np < 2; np++) {
                unsigned off = (unsigned)((warp_n + np * 16 + (lane >> 4) * 8 + (lane & 7)) * 128
                                          + ks * 32 + ((lane >> 3) & 1) * 16);
                ldsm_x4(bh2[np], buf + B_OFF + (off ^ ((off >> 3) & 0x70)));
            }
            #pragma unroll
            for (int mf = 0; mf < 2; mf++)
                #pragma unroll
                for (int np = 0; np < 2; np++)
                    #pragma unroll
                    for (int h = 0; h < 2; h++)
                        mma_bf16(acc[mf][np * 2 + h], ah[mf], &bh2[np][2 * h]);
        }
    }

    const int bbase = b * KCL;
    #pragma unroll
    for (int mf = 0; mf < 2; mf++) {
        int row = c0 + warp_m + mf * 16 + (lane >> 2);
        #pragma unroll
        for (int nf = 0; nf < 4; nf++) {
            int k = warp_n + nf * 8 + (lane & 3) * 2;
            float* g0 = g_agg + (size_t)(bbase + k) * CDIM + row;
            g0[0]        = acc[mf][nf][0];
            g0[CDIM]     = acc[mf][nf][1];
            g0[8]        = acc[mf][nf][2];
            g0[CDIM + 8] = acc[mf][nf][3];
        }
    }
#undef P2_ISSUE
}

// ---------------------------------------------------------------------------
// Pass 3: v = agg - centroid*mass; out = v/(max(||v||,eps)*8)
// (attention, ghost weighting and global norm cancel algebraically)
// ---------------------------------------------------------------------------
__global__ __launch_bounds__(128) void pass3(const float* __restrict__ centroids,
                                             float* __restrict__ out)
{
    const int k   = blockIdx.x;
    const int b   = blockIdx.y;
    const int tid = threadIdx.x;

    __shared__ float s_mass;
    __shared__ float s_red[4];

    if (tid == 0) {
        float m = 0.0f;
        #pragma unroll
        for (int t = 0; t < NTILES; t++) m += g_massp[((size_t)b * NTILES + t) * KCL + k];
        s_mass = m;
    }
    __syncthreads();
    const float mass = s_mass;

    float v[4];
    float ssq = 0.0f;
    #pragma unroll
    for (int j = 0; j < 4; j++) {
        int c = tid + 128 * j;
        float val = g_agg[((size_t)b * KCL + k) * CDIM + c] - centroids[k * CDIM + c] * mass;
        v[j] = val;
        ssq = fmaf(val, val, ssq);
    }
    #pragma unroll
    for (int o = 16; o > 0; o >>= 1) ssq += __shfl_xor_sync(0xffffffffu, ssq, o);
    if ((tid & 31) == 0) s_red[tid >> 5] = ssq;
    __syncthreads();
    float tot = s_red[0] + s_red[1] + s_red[2] + s_red[3];
    float scale = 1.0f / (fmaxf(sqrtf(tot), 1e-12f) * 8.0f);
    #pragma unroll
    for (int j = 0; j < 4; j++)
        out[((size_t)b * KCL + k) * CDIM + tid + 128 * j] = v[j] * scale;
}

// ---------------------------------------------------------------------------
extern "C" void kernel_launch(void* const* d_in, const int* in_sizes, int n_in,
                              void* d_out, int out_size)
{
    const float* x         = (const float*)d_in[0];
    const float* centroids = (const float*)d_in[1];
    const float* conv_w    = (const float*)d_in[2];
    const float* conv_b    = (const float*)d_in[3];
    float* out = (float*)d_out;

    cudaFuncSetAttribute(pass1, cudaFuncAttributeMaxDynamicSharedMemorySize, 64512);
    cudaFuncSetAttribute(pass2, cudaFuncAttributeMaxDynamicSharedMemorySize, 98304);

    pass1<<<dim3(NTILES, BATCH), 256, 64512>>>(x, conv_w, conv_b);
    pass2<<<dim3(4, BATCH), 256, 98304>>>();
    pass3<<<dim3(KCL, BATCH), 128>>>(centroids, out);
}

// round 9
// speedup vs baseline: 4.8630x; 1.0964x over previous
#include <cuda_runtime.h>
#include <cuda_bf16.h>
#include <math.h>
#include <stdint.h>

#define BATCH 32
#define CDIM  512
#define NDIM  4096
#define TCL   72
#define KCL   64
#define NT1   128
#define NTILES 32            // 4096/128

// Scratch (static device globals; no runtime allocation)
__device__ __nv_bfloat16 g_a2h[(size_t)BATCH * KCL * NDIM];   // assign*invn, bf16
__device__ __nv_bfloat16 g_xb[(size_t)BATCH * CDIM * NDIM];   // x in bf16
__device__ __nv_bfloat16 g_wb[8 * 80 * 64];                   // W bf16 [chunk][t(80)][c(64)]
__device__ float g_invn[(size_t)BATCH * NDIM];
__device__ float g_massp[(size_t)BATCH * NTILES * KCL];
__device__ float g_agg[(size_t)BATCH * KCL * CDIM];

__device__ __forceinline__ unsigned smem_u32(const void* p) {
    unsigned a;
    asm("{ .reg .u64 t; cvta.to.shared.u64 t, %1; cvt.u32.u64 %0, t; }" : "=r"(a) : "l"(p));
    return a;
}
__device__ __forceinline__ void ldsm_x4(uint32_t* r, unsigned addr) {
    asm volatile("ldmatrix.sync.aligned.m8n8.x4.shared.b16 {%0,%1,%2,%3}, [%4];"
                 : "=r"(r[0]), "=r"(r[1]), "=r"(r[2]), "=r"(r[3]) : "r"(addr));
}
__device__ __forceinline__ void ldsm_x4t(uint32_t* r, unsigned addr) {
    asm volatile("ldmatrix.sync.aligned.m8n8.x4.trans.shared.b16 {%0,%1,%2,%3}, [%4];"
                 : "=r"(r[0]), "=r"(r[1]), "=r"(r[2]), "=r"(r[3]) : "r"(addr));
}
__device__ __forceinline__ void mma_bf16(float* c, const uint32_t* a, const uint32_t* b) {
    asm volatile(
        "mma.sync.aligned.m16n8k16.row.col.f32.bf16.bf16.f32 "
        "{%0,%1,%2,%3},{%4,%5,%6,%7},{%8,%9},{%0,%1,%2,%3};"
        : "+f"(c[0]), "+f"(c[1]), "+f"(c[2]), "+f"(c[3])
        : "r"(a[0]), "r"(a[1]), "r"(a[2]), "r"(a[3]), "r"(b[0]), "r"(b[1]));
}
__device__ __forceinline__ void cpa16(unsigned dst, const void* src) {
    asm volatile("cp.async.cg.shared.global [%0], [%1], 16;" :: "r"(dst), "l"(src));
}
#define CP_COMMIT() asm volatile("cp.async.commit_group;")

// ---------------------------------------------------------------------------
// Pass 0: streaming x fp32 -> bf16 (g_xb) + per-(b,n) invn; W -> bf16 table.
// Blocks 0..127: (b, slab of 1024 n). Block 128: W conversion.
// ---------------------------------------------------------------------------
__global__ __launch_bounds__(256) void pass0(const float* __restrict__ x,
                                             const float* __restrict__ conv_w)
{
    const int tid = threadIdx.x;
    if (blockIdx.x == 128) {
        for (int i = tid; i < 80 * 512; i += 256) {
            int t = i >> 9, c = i & 511;
            float v = (t < TCL) ? conv_w[t * CDIM + c] : 0.0f;
            g_wb[(c >> 6) * 5120 + t * 64 + (c & 63)] = __float2bfloat16(v);
        }
        return;
    }
    const int b = blockIdx.x >> 2, slab = blockIdx.x & 3;
    const size_t base = (size_t)b * CDIM * NDIM + slab * 1024 + tid * 4;
    const float* xp = x + base;
    __nv_bfloat16* xo = g_xb + base;
    float s0 = 0.f, s1 = 0.f, s2 = 0.f, s3 = 0.f;
    #pragma unroll 8
    for (int c = 0; c < CDIM; c++) {
        float4 v = *(const float4*)(xp + (size_t)c * NDIM);
        s0 = fmaf(v.x, v.x, s0);
        s1 = fmaf(v.y, v.y, s1);
        s2 = fmaf(v.z, v.z, s2);
        s3 = fmaf(v.w, v.w, s3);
        __nv_bfloat162 h01 = __floats2bfloat162_rn(v.x, v.y);
        __nv_bfloat162 h23 = __floats2bfloat162_rn(v.z, v.w);
        uint2 u; u.x = *(unsigned*)&h01; u.y = *(unsigned*)&h23;
        *(uint2*)(xo + (size_t)c * NDIM) = u;
    }
    float4 inv;
    inv.x = 1.0f / fmaxf(sqrtf(s0), 1e-12f);
    inv.y = 1.0f / fmaxf(sqrtf(s1), 1e-12f);
    inv.z = 1.0f / fmaxf(sqrtf(s2), 1e-12f);
    inv.w = 1.0f / fmaxf(sqrtf(s3), 1e-12f);
    *(float4*)(g_invn + (size_t)b * NDIM + slab * 1024 + tid * 4) = inv;
}

// ---------------------------------------------------------------------------
// Pass 1 (pipelined HMMA GEMM + softmax): raw[n,t] = sum_c xb[c,n] W[t,c];
// logits = raw*invn + bias; softmax over t; a2 = assign*invn (bf16); mass.
// Block = 128 n x 80 t, K = 512 c in 8 chunks. 4-stage cp.async (26KB/stage).
// ---------------------------------------------------------------------------
#define P1_STG 26624u         // 16384 (X: 64c x 128n bf16, 256B rows) + 10240 (W)
#define P1_WOFF 16384u
#define P1_INVN 106496u
#define P1_BIAS 107008u
#define P1_LG   0u            // phase B: [128 n][84 t] fp32 (43008B)
#define P1_A2ST 43008u        // [64 k][128 n] bf16 (16384B)

__global__ __launch_bounds__(256) void pass1(const float* __restrict__ conv_b)
{
    extern __shared__ char sm[];
    const unsigned sb = smem_u32(sm);
    const int ntile = blockIdx.x;
    const int b     = blockIdx.y;
    const int n0    = ntile * NT1;
    const int tid   = threadIdx.x;
    const int lane  = tid & 31;
    const int wid   = tid >> 5;
    const int m0    = wid * 16;

    if (tid < 80) {
        float v = (tid < TCL) ? conv_b[tid] : 0.0f;
        *(float*)(sm + P1_BIAS + tid * 4) = v;
    }
    if (tid < 128)
        ((float*)(sm + P1_INVN))[tid] = g_invn[(size_t)b * NDIM + n0 + tid];

#define P1_ISSUE(ST, CH) do {                                                  \
        unsigned _buf = sb + (unsigned)(ST) * P1_STG;                          \
        const __nv_bfloat16* _xs = g_xb + (size_t)b * CDIM * NDIM              \
                                   + (size_t)(CH) * 64 * NDIM + n0;            \
        _Pragma("unroll")                                                      \
        for (int r = 0; r < 4; r++) {                                          \
            int idx = tid + 256 * r;                                           \
            int row = idx >> 4, pc = idx & 15;                                 \
            unsigned off = (unsigned)(row * 256 + pc * 16);                    \
            cpa16(_buf + (off ^ ((off >> 4) & 0x70)),                          \
                  _xs + (size_t)row * NDIM + pc * 8);                          \
        }                                                                      \
        const __nv_bfloat16* _ws = g_wb + (CH) * 5120;                         \
        _Pragma("unroll")                                                      \
        for (int r = 0; r < 3; r++) {                                          \
            int idx = tid + 256 * r;                                           \
            if (idx < 640) {                                                   \
                int t = idx >> 3, pc = idx & 7;                                \
                unsigned off = (unsigned)(t * 128 + pc * 16);                  \
                cpa16(_buf + P1_WOFF + (off ^ ((off >> 3) & 0x70)),            \
                      _ws + t * 64 + pc * 8);                                  \
            }                                                                  \
        }                                                                      \
    } while (0)

    P1_ISSUE(0, 0); CP_COMMIT();
    P1_ISSUE(1, 1); CP_COMMIT();
    P1_ISSUE(2, 2); CP_COMMIT();

    float acc[10][4];
    #pragma unroll
    for (int i = 0; i < 10; i++)
        #pragma unroll
        for (int j = 0; j < 4; j++) acc[i][j] = 0.0f;

    for (int ch = 0; ch < 8; ch++) {
        asm volatile("cp.async.wait_group 2;" ::: "memory");
        __syncthreads();
        if (ch + 3 < 8) P1_ISSUE((ch + 3) & 3, ch + 3);
        CP_COMMIT();

        const unsigned xb = sb + (unsigned)(ch & 3) * P1_STG;
        const unsigned wb = xb + P1_WOFF;
        #pragma unroll
        for (int ks = 0; ks < 4; ks++) {
            uint32_t a[4];
            {   // A^T: stored [c][n] 256B rows; trans -> row-major n x c frags
                int crow = ks * 16 + (lane & 7) + ((lane >> 4) & 1) * 8;
                int ncol = m0 + ((lane >> 3) & 1) * 8;
                unsigned off = (unsigned)(crow * 256 + ncol * 2);
                ldsm_x4t(a, xb + (off ^ ((off >> 4) & 0x70)));
            }
            #pragma unroll
            for (int nb = 0; nb < 5; nb++) {
                uint32_t bf[4];
                int trow = nb * 16 + ((lane >> 4) & 1) * 8 + (lane & 7);
                unsigned off = (unsigned)(trow * 128 + ks * 32 + ((lane >> 3) & 1) * 16);
                ldsm_x4(bf, wb + (off ^ ((off >> 3) & 0x70)));
                mma_bf16(acc[2 * nb],     a, &bf[0]);
                mma_bf16(acc[2 * nb + 1], a, &bf[2]);
            }
        }
    }
    __syncthreads();

    // fragments -> logits smem [128 n][84 t]
    {
        float* lg = (float*)(sm + P1_LG);
        const float* invn = (const float*)(sm + P1_INVN);
        const float* bias = (const float*)(sm + P1_BIAS);
        int r0 = m0 + (lane >> 2);
        float i0 = invn[r0], i1 = invn[r0 + 8];
        #pragma unroll
        for (int nb = 0; nb < 10; nb++) {
            int tc = nb * 8 + 2 * (lane & 3);
            float b0 = bias[tc], b1 = bias[tc + 1];
            lg[r0 * 84 + tc]           = acc[nb][0] * i0 + b0;
            lg[r0 * 84 + tc + 1]       = acc[nb][1] * i0 + b1;
            lg[(r0 + 8) * 84 + tc]     = acc[nb][2] * i1 + b0;
            lg[(r0 + 8) * 84 + tc + 1] = acc[nb][3] * i1 + b1;
        }
    }
    __syncthreads();

    // softmax per n; a2 (bf16) into staging; assign back into lg
    if (tid < 128) {
        float* row = (float*)(sm + P1_LG) + tid * 84;
        float invn_n = ((float*)(sm + P1_INVN))[tid];
        float mx = -1e30f;
        #pragma unroll 8
        for (int t = 0; t < TCL; t++) mx = fmaxf(mx, row[t]);
        float s = 0.0f;
        #pragma unroll 8
        for (int t = 0; t < TCL; t++) { float e = __expf(row[t] - mx); row[t] = e; s += e; }
        float inv_s = 1.0f / s;
        float a2s   = inv_s * invn_n;
        __nv_bfloat16* a2st = (__nv_bfloat16*)(sm + P1_A2ST);
        #pragma unroll 8
        for (int t = 0; t < TCL; t++) {
            float e = row[t];
            if (t < KCL) a2st[t * 128 + tid] = __float2bfloat16(e * a2s);
            row[t] = e * inv_s;
        }
    }
    __syncthreads();

    // coalesced a2 writeout: [64 k][128 n] bf16
    #pragma unroll
    for (int it = 0; it < 4; it++) {
        int idx = tid + 256 * it;
        int k = idx >> 4, qq = idx & 15;
        *(uint4*)((char*)(g_a2h + ((size_t)(b * KCL + k)) * NDIM + n0) + 16 * qq)
            = *(const uint4*)(sm + P1_A2ST + k * 256 + 16 * qq);
    }
    // mass partials (k<64 only; ghosts never read downstream)
    if (tid < KCL) {
        const float* lg = (const float*)(sm + P1_LG);
        float m = 0.0f;
        #pragma unroll 8
        for (int n = 0; n < NT1; n++) m += lg[n * 84 + tid];
        g_massp[((size_t)b * NTILES + ntile) * KCL + tid] = m;
    }
#undef P1_ISSUE
}

// ---------------------------------------------------------------------------
// Pass 2: HMMA bf16, 4-stage cp.async pipeline, no conversions.
// D[c,k] = sum_n xb[c,n]*a2[k,n]; M=128(c) N=64(k) K=4096(n), 64-n chunks.
// ---------------------------------------------------------------------------
#define STG_SZ 24576u
#define B_OFF  16384u

__global__ __launch_bounds__(256) void pass2()
{
    extern __shared__ char smem[];
    const unsigned sbase = smem_u32(smem);
    const int ct   = blockIdx.x;
    const int b    = blockIdx.y;
    const int c0   = ct * 128;
    const int tid  = threadIdx.x;
    const int lane = tid & 31;
    const int wid  = tid >> 5;
    const int warp_m = (wid & 3) * 32;
    const int warp_n = (wid >> 2) * 32;

    const __nv_bfloat16* xsrc = g_xb + ((size_t)b * CDIM + c0) * NDIM;
    const __nv_bfloat16* asrc = g_a2h + (size_t)b * KCL * NDIM;

#define P2_ISSUE(ST, CH) do {                                                  \
        unsigned _buf = sbase + (unsigned)(ST) * STG_SZ;                       \
        _Pragma("unroll")                                                      \
        for (int r = 0; r < 4; r++) {                                          \
            int g = tid + 256 * r; int row = g >> 3, c16 = g & 7;              \
            unsigned off = (unsigned)(row * 128 + c16 * 16);                   \
            cpa16(_buf + (off ^ ((off >> 3) & 0x70)),                          \
                  xsrc + (size_t)row * NDIM + (CH) * 64 + c16 * 8);            \
        }                                                                      \
        _Pragma("unroll")                                                      \
        for (int r = 0; r < 2; r++) {                                          \
            int g = tid + 256 * r; int k = g >> 3, c16 = g & 7;                \
            unsigned off = (unsigned)(k * 128 + c16 * 16);                     \
            cpa16(_buf + B_OFF + (off ^ ((off >> 3) & 0x70)),                  \
                  asrc + (size_t)k * NDIM + (CH) * 64 + c16 * 8);              \
        }                                                                      \
    } while (0)

    P2_ISSUE(0, 0); CP_COMMIT();
    P2_ISSUE(1, 1); CP_COMMIT();
    P2_ISSUE(2, 2); CP_COMMIT();

    float acc[2][4][4];
    #pragma unroll
    for (int i = 0; i < 2; i++)
        #pragma unroll
        for (int j = 0; j < 4; j++)
            #pragma unroll
            for (int q = 0; q < 4; q++) acc[i][j][q] = 0.0f;

    for (int ch = 0; ch < 64; ch++) {
        asm volatile("cp.async.wait_group 2;" ::: "memory");
        __syncthreads();
        if (ch + 3 < 64) P2_ISSUE((ch + 3) & 3, ch + 3);
        CP_COMMIT();

        const unsigned buf = sbase + (unsigned)(ch & 3) * STG_SZ;
        #pragma unroll
        for (int ks = 0; ks < 4; ks++) {
            uint32_t ah[2][4], bh2[2][4];
            #pragma unroll
            for (int mf = 0; mf < 2; mf++) {
                unsigned off = (unsigned)((warp_m + mf * 16 + (lane & 15)) * 128
                                          + ks * 32 + (lane >> 4) * 16);
                ldsm_x4(ah[mf], buf + (off ^ ((off >> 3) & 0x70)));
            }
            #pragma unroll
            for (int np = 0; np < 2; np++) {
                unsigned off = (unsigned)((warp_n + np * 16 + (lane >> 4) * 8 + (lane & 7)) * 128
                                          + ks * 32 + ((lane >> 3) & 1) * 16);
                ldsm_x4(bh2[np], buf + B_OFF + (off ^ ((off >> 3) & 0x70)));
            }
            #pragma unroll
            for (int mf = 0; mf < 2; mf++)
                #pragma unroll
                for (int np = 0; np < 2; np++)
                    #pragma unroll
                    for (int h = 0; h < 2; h++)
                        mma_bf16(acc[mf][np * 2 + h], ah[mf], &bh2[np][2 * h]);
        }
    }

    const int bbase = b * KCL;
    #pragma unroll
    for (int mf = 0; mf < 2; mf++) {
        int row = c0 + warp_m + mf * 16 + (lane >> 2);
        #pragma unroll
        for (int nf = 0; nf < 4; nf++) {
            int k = warp_n + nf * 8 + (lane & 3) * 2;
            float* g0 = g_agg + (size_t)(bbase + k) * CDIM + row;
            g0[0]        = acc[mf][nf][0];
            g0[CDIM]     = acc[mf][nf][1];
            g0[8]        = acc[mf][nf][2];
            g0[CDIM + 8] = acc[mf][nf][3];
        }
    }
#undef P2_ISSUE
}

// ---------------------------------------------------------------------------
// Pass 3: v = agg - centroid*mass; out = v/(max(||v||,eps)*8)
// (attention, ghost weighting and global norm cancel algebraically)
// ---------------------------------------------------------------------------
__global__ __launch_bounds__(128) void pass3(const float* __restrict__ centroids,
                                             float* __restrict__ out)
{
    const int k   = blockIdx.x;
    const int b   = blockIdx.y;
    const int tid = threadIdx.x;

    __shared__ float s_mass;
    __shared__ float s_red[4];

    if (tid == 0) {
        float m = 0.0f;
        #pragma unroll
        for (int t = 0; t < NTILES; t++) m += g_massp[((size_t)b * NTILES + t) * KCL + k];
        s_mass = m;
    }
    __syncthreads();
    const float mass = s_mass;

    float v[4];
    float ssq = 0.0f;
    #pragma unroll
    for (int j = 0; j < 4; j++) {
        int c = tid + 128 * j;
        float val = g_agg[((size_t)b * KCL + k) * CDIM + c] - centroids[k * CDIM + c] * mass;
        v[j] = val;
        ssq = fmaf(val, val, ssq);
    }
    #pragma unroll
    for (int o = 16; o > 0; o >>= 1) ssq += __shfl_xor_sync(0xffffffffu, ssq, o);
    if ((tid & 31) == 0) s_red[tid >> 5] = ssq;
    __syncthreads();
    float tot = s_red[0] + s_red[1] + s_red[2] + s_red[3];
    float scale = 1.0f / (fmaxf(sqrtf(tot), 1e-12f) * 8.0f);
    #pragma unroll
    for (int j = 0; j < 4; j++)
        out[((size_t)b * KCL + k) * CDIM + tid + 128 * j] = v[j] * scale;
}

// ---------------------------------------------------------------------------
extern "C" void kernel_launch(void* const* d_in, const int* in_sizes, int n_in,
                              void* d_out, int out_size)
{
    const float* x         = (const float*)d_in[0];
    const float* centroids = (const float*)d_in[1];
    const float* conv_w    = (const float*)d_in[2];
    const float* conv_b    = (const float*)d_in[3];
    float* out = (float*)d_out;

    cudaFuncSetAttribute(pass1, cudaFuncAttributeMaxDynamicSharedMemorySize, 107328);
    cudaFuncSetAttribute(pass2, cudaFuncAttributeMaxDynamicSharedMemorySize, 98304);

    pass0<<<129, 256>>>(x, conv_w);
    pass1<<<dim3(NTILES, BATCH), 256, 107328>>>(conv_b);
    pass2<<<dim3(4, BATCH), 256, 98304>>>();
    pass3<<<dim3(KCL, BATCH), 128>>>(centroids, out);
}

// round 10
// speedup vs baseline: 6.0533x; 1.2448x over previous
#include <cuda_runtime.h>
#include <cuda_bf16.h>
#include <math.h>
#include <stdint.h>

#define BATCH 32
#define CDIM  512
#define NDIM  4096
#define TCL   72
#define KCL   64
#define NT1   256
#define NTILES 16            // 4096/256

// Scratch (static device globals; no runtime allocation)
__device__ __nv_bfloat16 g_a2h[(size_t)BATCH * KCL * NDIM];   // assign*invn, bf16
__device__ __nv_bfloat16 g_xb[(size_t)BATCH * CDIM * NDIM];   // x in bf16
__device__ __nv_bfloat16 g_wb[8 * 80 * 64];                   // W bf16 [chunk][t(80)][c(64)]
__device__ float g_ssqp[(size_t)4 * BATCH * NDIM];            // partial ssq (4 c-groups)
__device__ float g_massp[(size_t)BATCH * NTILES * KCL];
__device__ float g_agg[(size_t)BATCH * KCL * CDIM];

__device__ __forceinline__ unsigned smem_u32(const void* p) {
    unsigned a;
    asm("{ .reg .u64 t; cvta.to.shared.u64 t, %1; cvt.u32.u64 %0, t; }" : "=r"(a) : "l"(p));
    return a;
}
__device__ __forceinline__ void ldsm_x4(uint32_t* r, unsigned addr) {
    asm volatile("ldmatrix.sync.aligned.m8n8.x4.shared.b16 {%0,%1,%2,%3}, [%4];"
                 : "=r"(r[0]), "=r"(r[1]), "=r"(r[2]), "=r"(r[3]) : "r"(addr));
}
__device__ __forceinline__ void ldsm_x4t(uint32_t* r, unsigned addr) {
    asm volatile("ldmatrix.sync.aligned.m8n8.x4.trans.shared.b16 {%0,%1,%2,%3}, [%4];"
                 : "=r"(r[0]), "=r"(r[1]), "=r"(r[2]), "=r"(r[3]) : "r"(addr));
}
__device__ __forceinline__ void mma_bf16(float* c, const uint32_t* a, const uint32_t* b) {
    asm volatile(
        "mma.sync.aligned.m16n8k16.row.col.f32.bf16.bf16.f32 "
        "{%0,%1,%2,%3},{%4,%5,%6,%7},{%8,%9},{%0,%1,%2,%3};"
        : "+f"(c[0]), "+f"(c[1]), "+f"(c[2]), "+f"(c[3])
        : "r"(a[0]), "r"(a[1]), "r"(a[2]), "r"(a[3]), "r"(b[0]), "r"(b[1]));
}
__device__ __forceinline__ void cpa16(unsigned dst, const void* src) {
    asm volatile("cp.async.cg.shared.global [%0], [%1], 16;" :: "r"(dst), "l"(src));
}
#define CP_COMMIT() asm volatile("cp.async.commit_group;")

// ---------------------------------------------------------------------------
// Pass 0: streaming x fp32 -> bf16 (g_xb) + partial ssq (4 c-groups); W table.
// Grid (17, 32): x<16 -> (cgrp = x>>2, slab = x&3) over b = y; x==16,y==0 -> W.
// ---------------------------------------------------------------------------
__global__ __launch_bounds__(256) void pass0(const float* __restrict__ x,
                                             const float* __restrict__ conv_w)
{
    const int tid = threadIdx.x;
    if (blockIdx.x == 16) {
        if (blockIdx.y == 0) {
            for (int i = tid; i < 80 * 512; i += 256) {
                int t = i >> 9, c = i & 511;
                float v = (t < TCL) ? conv_w[t * CDIM + c] : 0.0f;
                g_wb[(c >> 6) * 5120 + t * 64 + (c & 63)] = __float2bfloat16(v);
            }
        }
        return;
    }
    const int b    = blockIdx.y;
    const int cgrp = blockIdx.x >> 2;
    const int slab = blockIdx.x & 3;
    const size_t nbase = (size_t)slab * 1024 + tid * 4;
    const size_t base = (size_t)b * CDIM * NDIM + (size_t)(cgrp * 128) * NDIM + nbase;
    const float* xp = x + base;
    __nv_bfloat16* xo = g_xb + base;
    float s0 = 0.f, s1 = 0.f, s2 = 0.f, s3 = 0.f;
    #pragma unroll 8
    for (int c = 0; c < 128; c++) {
        float4 v = *(const float4*)(xp + (size_t)c * NDIM);
        s0 = fmaf(v.x, v.x, s0);
        s1 = fmaf(v.y, v.y, s1);
        s2 = fmaf(v.z, v.z, s2);
        s3 = fmaf(v.w, v.w, s3);
        __nv_bfloat162 h01 = __floats2bfloat162_rn(v.x, v.y);
        __nv_bfloat162 h23 = __floats2bfloat162_rn(v.z, v.w);
        uint2 u; u.x = *(unsigned*)&h01; u.y = *(unsigned*)&h23;
        *(uint2*)(xo + (size_t)c * NDIM) = u;
    }
    *(float4*)(g_ssqp + (size_t)(b * 4 + cgrp) * NDIM + nbase) = make_float4(s0, s1, s2, s3);
}

// ---------------------------------------------------------------------------
// Pass 1 (pipelined HMMA GEMM + softmax): raw[n,t] = sum_c xb[c,n] W[t,c];
// logits = raw*invn + bias; softmax over t; a2 = assign*invn (bf16); mass.
// Block = 256 n x 80 t, K = 512 c in 8 chunks. 4-stage cp.async (32KB X each);
// W (all 8 chunks, 80KB) resident, loaded in the first group.
// ---------------------------------------------------------------------------
#define P1_STG  32768u        // X stage: 64c x 256n bf16, 512B rows, swz >>5
#define P1_WOFF 131072u       // W: 8 x [80t][64c] bf16, 128B rows, swz >>3
#define P1_INVN 212992u
#define P1_BIAS 214016u
#define P1_LG   0u            // phase B: [256 n][84 t] fp32 (86016B)
#define P1_A2ST 86016u        // [64 k][256 n] bf16 (32768B)

__global__ __launch_bounds__(256) void pass1(const float* __restrict__ conv_b)
{
    extern __shared__ char sm[];
    const unsigned sb = smem_u32(sm);
    const int ntile = blockIdx.x;
    const int b     = blockIdx.y;
    const int n0    = ntile * NT1;
    const int tid   = threadIdx.x;
    const int lane  = tid & 31;
    const int wid   = tid >> 5;

    if (tid < 80) {
        float v = (tid < TCL) ? conv_b[tid] : 0.0f;
        *(float*)(sm + P1_BIAS + tid * 4) = v;
    }
    {   // invn from 4 ssq partials
        float s = 0.0f;
        #pragma unroll
        for (int cg = 0; cg < 4; cg++)
            s += g_ssqp[(size_t)(b * 4 + cg) * NDIM + n0 + tid];
        ((float*)(sm + P1_INVN))[tid] = 1.0f / fmaxf(sqrtf(s), 1e-12f);
    }

#define P1_ISSUE(ST, CH) do {                                                  \
        unsigned _buf = sb + (unsigned)(ST) * P1_STG;                          \
        const __nv_bfloat16* _xs = g_xb + (size_t)b * CDIM * NDIM              \
                                   + (size_t)(CH) * 64 * NDIM + n0;            \
        _Pragma("unroll")                                                      \
        for (int r = 0; r < 8; r++) {                                          \
            int idx = tid + 256 * r;                                           \
            int row = idx >> 5, pc = idx & 31;                                 \
            unsigned off = (unsigned)(row * 512 + pc * 16);                    \
            cpa16(_buf + (off ^ ((off >> 5) & 0x70)),                          \
                  _xs + (size_t)row * NDIM + pc * 8);                          \
        }                                                                      \
    } while (0)

    // group 0: all W + stage 0
    #pragma unroll
    for (int r = 0; r < 20; r++) {
        int idx = tid + 256 * r;
        int chw = idx / 640, rem = idx - chw * 640;
        int t = rem >> 3, pc = rem & 7;
        unsigned off = (unsigned)(t * 128 + pc * 16);
        cpa16(sb + P1_WOFF + chw * 10240 + (off ^ ((off >> 3) & 0x70)),
              g_wb + chw * 5120 + t * 64 + pc * 8);
    }
    P1_ISSUE(0, 0); CP_COMMIT();
    P1_ISSUE(1, 1); CP_COMMIT();
    P1_ISSUE(2, 2); CP_COMMIT();

    float acc[2][10][4];
    #pragma unroll
    for (int mf = 0; mf < 2; mf++)
        #pragma unroll
        for (int i = 0; i < 10; i++)
            #pragma unroll
            for (int j = 0; j < 4; j++) acc[mf][i][j] = 0.0f;

    for (int ch = 0; ch < 8; ch++) {
        asm volatile("cp.async.wait_group 2;" ::: "memory");
        __syncthreads();
        if (ch + 3 < 8) P1_ISSUE((ch + 3) & 3, ch + 3);
        CP_COMMIT();

        const unsigned xb = sb + (unsigned)(ch & 3) * P1_STG;
        const unsigned wb = sb + P1_WOFF + (unsigned)ch * 10240u;
        #pragma unroll
        for (int ks = 0; ks < 4; ks++) {
            uint32_t a[2][4];
            #pragma unroll
            for (int mf = 0; mf < 2; mf++) {
                // A^T: [c][n] 512B rows; trans -> row-major n x c frags
                int crow = ks * 16 + (lane & 7) + ((lane >> 4) & 1) * 8;
                int ncol = wid * 32 + mf * 16 + ((lane >> 3) & 1) * 8;
                unsigned off = (unsigned)(crow * 512 + ncol * 2);
                ldsm_x4t(a[mf], xb + (off ^ ((off >> 5) & 0x70)));
            }
            #pragma unroll
            for (int nb = 0; nb < 5; nb++) {
                uint32_t bf[4];
                int trow = nb * 16 + ((lane >> 4) & 1) * 8 + (lane & 7);
                unsigned off = (unsigned)(trow * 128 + ks * 32 + ((lane >> 3) & 1) * 16);
                ldsm_x4(bf, wb + (off ^ ((off >> 3) & 0x70)));
                #pragma unroll
                for (int mf = 0; mf < 2; mf++) {
                    mma_bf16(acc[mf][2 * nb],     a[mf], &bf[0]);
                    mma_bf16(acc[mf][2 * nb + 1], a[mf], &bf[2]);
                }
            }
        }
    }
    __syncthreads();

    // fragments -> logits smem [256 n][84 t]
    {
        float* lg = (float*)(sm + P1_LG);
        const float* invn = (const float*)(sm + P1_INVN);
        const float* bias = (const float*)(sm + P1_BIAS);
        #pragma unroll
        for (int mf = 0; mf < 2; mf++) {
            int r0 = wid * 32 + mf * 16 + (lane >> 2);
            float i0 = invn[r0], i1 = invn[r0 + 8];
            #pragma unroll
            for (int nb = 0; nb < 10; nb++) {
                int tc = nb * 8 + 2 * (lane & 3);
                float b0 = bias[tc], b1 = bias[tc + 1];
                lg[r0 * 84 + tc]           = acc[mf][nb][0] * i0 + b0;
                lg[r0 * 84 + tc + 1]       = acc[mf][nb][1] * i0 + b1;
                lg[(r0 + 8) * 84 + tc]     = acc[mf][nb][2] * i1 + b0;
                lg[(r0 + 8) * 84 + tc + 1] = acc[mf][nb][3] * i1 + b1;
            }
        }
    }
    __syncthreads();

    // softmax per n (all 256 threads); a2 (bf16) into staging
    {
        float* row = (float*)(sm + P1_LG) + tid * 84;
        float invn_n = ((float*)(sm + P1_INVN))[tid];
        float mx = -1e30f;
        #pragma unroll 8
        for (int t = 0; t < TCL; t++) mx = fmaxf(mx, row[t]);
        float s = 0.0f;
        #pragma unroll 8
        for (int t = 0; t < TCL; t++) { float e = __expf(row[t] - mx); row[t] = e; s += e; }
        float inv_s = 1.0f / s;
        float a2s   = inv_s * invn_n;
        __nv_bfloat16* a2st = (__nv_bfloat16*)(sm + P1_A2ST);
        #pragma unroll 8
        for (int t = 0; t < TCL; t++) {
            float e = row[t];
            if (t < KCL) a2st[t * 256 + tid] = __float2bfloat16(e * a2s);
            row[t] = e * inv_s;
        }
    }
    __syncthreads();

    // coalesced a2 writeout: [64 k][256 n] bf16 = 32KB
    #pragma unroll
    for (int it = 0; it < 8; it++) {
        int idx = tid + 256 * it;
        int k = idx >> 5, qq = idx & 31;
        *(uint4*)((char*)(g_a2h + ((size_t)(b * KCL + k)) * NDIM + n0) + 16 * qq)
            = *(const uint4*)(sm + P1_A2ST + k * 512 + 16 * qq);
    }
    // mass partials (k<64 only; ghosts never read downstream)
    if (tid < KCL) {
        const float* lg = (const float*)(sm + P1_LG);
        float m = 0.0f;
        #pragma unroll 8
        for (int n = 0; n < NT1; n++) m += lg[n * 84 + tid];
        g_massp[((size_t)b * NTILES + ntile) * KCL + tid] = m;
    }
#undef P1_ISSUE
}

// ---------------------------------------------------------------------------
// Pass 2: HMMA bf16, 4-stage cp.async pipeline, no conversions.
// D[c,k] = sum_n xb[c,n]*a2[k,n]; M=128(c) N=64(k) K=4096(n), 64-n chunks.
// ---------------------------------------------------------------------------
#define STG_SZ 24576u
#define B_OFF  16384u

__global__ __launch_bounds__(256) void pass2()
{
    extern __shared__ char smem[];
    const unsigned sbase = smem_u32(smem);
    const int ct   = blockIdx.x;
    const int b    = blockIdx.y;
    const int c0   = ct * 128;
    const int tid  = threadIdx.x;
    const int lane = tid & 31;
    const int wid  = tid >> 5;
    const int warp_m = (wid & 3) * 32;
    const int warp_n = (wid >> 2) * 32;

    const __nv_bfloat16* xsrc = g_xb + ((size_t)b * CDIM + c0) * NDIM;
    const __nv_bfloat16* asrc = g_a2h + (size_t)b * KCL * NDIM;

#define P2_ISSUE(ST, CH) do {                                                  \
        unsigned _buf = sbase + (unsigned)(ST) * STG_SZ;                       \
        _Pragma("unroll")                                                      \
        for (int r = 0; r < 4; r++) {                                          \
            int g = tid + 256 * r; int row = g >> 3, c16 = g & 7;              \
            unsigned off = (unsigned)(row * 128 + c16 * 16);                   \
            cpa16(_buf + (off ^ ((off >> 3) & 0x70)),                          \
                  xsrc + (size_t)row * NDIM + (CH) * 64 + c16 * 8);            \
        }                                                                      \
        _Pragma("unroll")                                                      \
        for (int r = 0; r < 2; r++) {                                          \
            int g = tid + 256 * r; int k = g >> 3, c16 = g & 7;                \
            unsigned off = (unsigned)(k * 128 + c16 * 16);                     \
            cpa16(_buf + B_OFF + (off ^ ((off >> 3) & 0x70)),                  \
                  asrc + (size_t)k * NDIM + (CH) * 64 + c16 * 8);              \
        }                                                                      \
    } while (0)

    P2_ISSUE(0, 0); CP_COMMIT();
    P2_ISSUE(1, 1); CP_COMMIT();
    P2_ISSUE(2, 2); CP_COMMIT();

    float acc[2][4][4];
    #pragma unroll
    for (int i = 0; i < 2; i++)
        #pragma unroll
        for (int j = 0; j < 4; j++)
            #pragma unroll
            for (int q = 0; q < 4; q++) acc[i][j][q] = 0.0f;

    for (int ch = 0; ch < 64; ch++) {
        asm volatile("cp.async.wait_group 2;" ::: "memory");
        __syncthreads();
        if (ch + 3 < 64) P2_ISSUE((ch + 3) & 3, ch + 3);
        CP_COMMIT();

        const unsigned buf = sbase + (unsigned)(ch & 3) * STG_SZ;
        #pragma unroll
        for (int ks = 0; ks < 4; ks++) {
            uint32_t ah[2][4], bh2[2][4];
            #pragma unroll
            for (int mf = 0; mf < 2; mf++) {
                unsigned off = (unsigned)((warp_m + mf * 16 + (lane & 15)) * 128
                                          + ks * 32 + (lane >> 4) * 16);
                ldsm_x4(ah[mf], buf + (off ^ ((off >> 3) & 0x70)));
            }
            #pragma unroll
            for (int np = 0; np < 2; np++) {
                unsigned off = (unsigned)((warp_n + np * 16 + (lane >> 4) * 8 + (lane & 7)) * 128
                                          + ks * 32 + ((lane >> 3) & 1) * 16);
                ldsm_x4(bh2[np], buf + B_OFF + (off ^ ((off >> 3) & 0x70)));
            }
            #pragma unroll
            for (int mf = 0; mf < 2; mf++)
                #pragma unroll
                for (int np = 0; np < 2; np++)
                    #pragma unroll
                    for (int h = 0; h < 2; h++)
                        mma_bf16(acc[mf][np * 2 + h], ah[mf], &bh2[np][2 * h]);
        }
    }

    const int bbase = b * KCL;
    #pragma unroll
    for (int mf = 0; mf < 2; mf++) {
        int row = c0 + warp_m + mf * 16 + (lane >> 2);
        #pragma unroll
        for (int nf = 0; nf < 4; nf++) {
            int k = warp_n + nf * 8 + (lane & 3) * 2;
            float* g0 = g_agg + (size_t)(bbase + k) * CDIM + row;
            g0[0]        = acc[mf][nf][0];
            g0[CDIM]     = acc[mf][nf][1];
            g0[8]        = acc[mf][nf][2];
            g0[CDIM + 8] = acc[mf][nf][3];
        }
    }
#undef P2_ISSUE
}

// ---------------------------------------------------------------------------
// Pass 3: v = agg - centroid*mass; out = v/(max(||v||,eps)*8)
// (attention, ghost weighting and global norm cancel algebraically)
// ---------------------------------------------------------------------------
__global__ __launch_bounds__(128) void pass3(const float* __restrict__ centroids,
                                             float* __restrict__ out)
{
    const int k   = blockIdx.x;
    const int b   = blockIdx.y;
    const int tid = threadIdx.x;

    __shared__ float s_mass;
    __shared__ float s_red[4];

    if (tid == 0) {
        float m = 0.0f;
        #pragma unroll
        for (int t = 0; t < NTILES; t++) m += g_massp[((size_t)b * NTILES + t) * KCL + k];
        s_mass = m;
    }
    __syncthreads();
    const float mass = s_mass;

    float v[4];
    float ssq = 0.0f;
    #pragma unroll
    for (int j = 0; j < 4; j++) {
        int c = tid + 128 * j;
        float val = g_agg[((size_t)b * KCL + k) * CDIM + c] - centroids[k * CDIM + c] * mass;
        v[j] = val;
        ssq = fmaf(val, val, ssq);
    }
    #pragma unroll
    for (int o = 16; o > 0; o >>= 1) ssq += __shfl_xor_sync(0xffffffffu, ssq, o);
    if ((tid & 31) == 0) s_red[tid >> 5] = ssq;
    __syncthreads();
    float tot = s_red[0] + s_red[1] + s_red[2] + s_red[3];
    float scale = 1.0f / (fmaxf(sqrtf(tot), 1e-12f) * 8.0f);
    #pragma unroll
    for (int j = 0; j < 4; j++)
        out[((size_t)b * KCL + k) * CDIM + tid + 128 * j] = v[j] * scale;
}

// ---------------------------------------------------------------------------
extern "C" void kernel_launch(void* const* d_in, const int* in_sizes, int n_in,
                              void* d_out, int out_size)
{
    const float* x         = (const float*)d_in[0];
    const float* centroids = (const float*)d_in[1];
    const float* conv_w    = (const float*)d_in[2];
    const float* conv_b    = (const float*)d_in[3];
    float* out = (float*)d_out;

    cudaFuncSetAttribute(pass1, cudaFuncAttributeMaxDynamicSharedMemorySize, 214336);
    cudaFuncSetAttribute(pass2, cudaFuncAttributeMaxDynamicSharedMemorySize, 98304);

    pass0<<<dim3(17, BATCH), 256>>>(x, conv_w);
    pass1<<<dim3(NTILES, BATCH), 256, 214336>>>(conv_b);
    pass2<<<dim3(4, BATCH), 256, 98304>>>();
    pass3<<<dim3(KCL, BATCH), 128>>>(centroids, out);
}

// round 11
// speedup vs baseline: 6.2445x; 1.0316x over previous
#include <cuda_runtime.h>
#include <cuda_bf16.h>
#include <math.h>
#include <stdint.h>

#define BATCH 32
#define CDIM  512
#define NDIM  4096
#define TCL   72
#define KCL   64
#define NT1   256
#define NTILES 16            // 4096/256

// Scratch (static device globals; no runtime allocation)
__device__ __nv_bfloat16 g_a2h[(size_t)BATCH * KCL * NDIM];   // assign*invn, bf16
__device__ __nv_bfloat16 g_xb[(size_t)BATCH * CDIM * NDIM];   // x in bf16 (for pass2)
__device__ __nv_bfloat16 g_wb[8 * 80 * 64];                   // W bf16 [chunk][t(80)][c(64)]
__device__ float g_massp[(size_t)BATCH * NTILES * KCL];
__device__ float g_agg[(size_t)BATCH * KCL * CDIM];

__device__ __forceinline__ unsigned smem_u32(const void* p) {
    unsigned a;
    asm("{ .reg .u64 t; cvta.to.shared.u64 t, %1; cvt.u32.u64 %0, t; }" : "=r"(a) : "l"(p));
    return a;
}
__device__ __forceinline__ void ldsm_x4(uint32_t* r, unsigned addr) {
    asm volatile("ldmatrix.sync.aligned.m8n8.x4.shared.b16 {%0,%1,%2,%3}, [%4];"
                 : "=r"(r[0]), "=r"(r[1]), "=r"(r[2]), "=r"(r[3]) : "r"(addr));
}
__device__ __forceinline__ void ldsm_x4t(uint32_t* r, unsigned addr) {
    asm volatile("ldmatrix.sync.aligned.m8n8.x4.trans.shared.b16 {%0,%1,%2,%3}, [%4];"
                 : "=r"(r[0]), "=r"(r[1]), "=r"(r[2]), "=r"(r[3]) : "r"(addr));
}
__device__ __forceinline__ void mma_bf16(float* c, const uint32_t* a, const uint32_t* b) {
    asm volatile(
        "mma.sync.aligned.m16n8k16.row.col.f32.bf16.bf16.f32 "
        "{%0,%1,%2,%3},{%4,%5,%6,%7},{%8,%9},{%0,%1,%2,%3};"
        : "+f"(c[0]), "+f"(c[1]), "+f"(c[2]), "+f"(c[3])
        : "r"(a[0]), "r"(a[1]), "r"(a[2]), "r"(a[3]), "r"(b[0]), "r"(b[1]));
}
__device__ __forceinline__ void sts_v2(unsigned addr, __nv_bfloat162 p0, __nv_bfloat162 p1) {
    asm volatile("st.shared.v2.b32 [%0], {%1,%2};"
                 :: "r"(addr), "r"(*(unsigned*)&p0), "r"(*(unsigned*)&p1));
}
__device__ __forceinline__ void cpa16(unsigned dst, const void* src) {
    asm volatile("cp.async.cg.shared.global [%0], [%1], 16;" :: "r"(dst), "l"(src));
}
#define CP_COMMIT() asm volatile("cp.async.commit_group;")

// ---------------------------------------------------------------------------
// Pass 0w: W fp32 -> bf16 table (tiny; grid 1)
// ---------------------------------------------------------------------------
__global__ __launch_bounds__(256) void pass0w(const float* __restrict__ conv_w)
{
    const int tid = threadIdx.x;
    for (int i = tid; i < 80 * 512; i += 256) {
        int t = i >> 9, c = i & 511;
        float v = (t < TCL) ? conv_w[t * CDIM + c] : 0.0f;
        g_wb[(c >> 6) * 5120 + t * 64 + (c & 63)] = __float2bfloat16(v);
    }
}

// ---------------------------------------------------------------------------
// Pass 1 (fused convert + HMMA GEMM + softmax):
// cp.async fp32 x stages (32c x 256n, 3 stages) -> convert (ssq, bf16 xbuf,
// g_xb writeout) -> MMA vs resident W. Then invn, logits, softmax, a2, mass.
// ---------------------------------------------------------------------------
#define P1_STG   32768u       // fp32 stage: 32c x 256n fp32, rows 1024B (no swz)
#define P1_WOFF  98304u       // W: 8 x [80t][64c] bf16, 128B rows, swz >>3
#define P1_XBUF  180224u      // 2 x (32c x 256n bf16, 512B rows, swz >>5)
#define P1_SSQS  212992u      // [4 cb][64 q][4] fp32 = 4KB
#define P1_INVN  217088u      // 256 fp32
#define P1_BIAS  218112u      // 80 fp32
#define P1_SMEM  218496
#define P1_LG    0u           // phase B: [256 n][84 t] fp32 (86016B)
#define P1_A2ST  86016u       // [64 k][256 n] bf16 (32768B)

__global__ __launch_bounds__(256) void pass1(const float* __restrict__ x,
                                             const float* __restrict__ conv_b)
{
    extern __shared__ char sm[];
    const unsigned sb = smem_u32(sm);
    const int ntile = blockIdx.x;
    const int b     = blockIdx.y;
    const int n0    = ntile * NT1;
    const int tid   = threadIdx.x;
    const int lane  = tid & 31;
    const int wid   = tid >> 5;

    if (tid < 80) {
        float v = (tid < TCL) ? conv_b[tid] : 0.0f;
        *(float*)(sm + P1_BIAS + tid * 4) = v;
    }

    const float* xsrc = x + (size_t)b * CDIM * NDIM + n0;

#define P1_ISSUE(ST, CH) do {                                                  \
        unsigned _buf = sb + (unsigned)(ST) * P1_STG;                          \
        const float* _xs = xsrc + (size_t)(CH) * 32 * NDIM;                    \
        _Pragma("unroll")                                                      \
        for (int r = 0; r < 8; r++) {                                          \
            int idx = tid + 256 * r;                                           \
            int c = idx >> 6, q = idx & 63;                                    \
            cpa16(_buf + (unsigned)(c * 1024 + q * 16),                        \
                  _xs + (size_t)c * NDIM + 4 * q);                             \
        }                                                                      \
    } while (0)

    // group 0: all W + stage 0
    #pragma unroll
    for (int r = 0; r < 20; r++) {
        int idx = tid + 256 * r;
        int chw = idx / 640, rem = idx - chw * 640;
        int t = rem >> 3, pc = rem & 7;
        unsigned off = (unsigned)(t * 128 + pc * 16);
        cpa16(sb + P1_WOFF + chw * 10240 + (off ^ ((off >> 3) & 0x70)),
              g_wb + chw * 5120 + t * 64 + pc * 8);
    }
    P1_ISSUE(0, 0); CP_COMMIT();
    P1_ISSUE(1, 1); CP_COMMIT();
    P1_ISSUE(2, 2); CP_COMMIT();

    float acc[2][10][4];
    #pragma unroll
    for (int mf = 0; mf < 2; mf++)
        #pragma unroll
        for (int i = 0; i < 10; i++)
            #pragma unroll
            for (int j = 0; j < 4; j++) acc[mf][i][j] = 0.0f;
    float ssq4[4] = {0.f, 0.f, 0.f, 0.f};

    const int cb = tid >> 6;       // 0..3 (c sub-block)
    const int qq = tid & 63;       // float4 group (4 n)
    __nv_bfloat16* xbo = g_xb + (size_t)b * CDIM * NDIM + n0 + 4 * qq;

    for (int ch = 0; ch < 16; ch++) {
        asm volatile("cp.async.wait_group 2;" ::: "memory");
        __syncthreads();

        // convert: fp32 stage -> ssq + bf16 xbuf + g_xb
        {
            const char* stg = sm + (unsigned)(ch % 3) * P1_STG;
            const unsigned xbuf = sb + P1_XBUF + (unsigned)(ch & 1) * 16384u;
            #pragma unroll
            for (int r = 0; r < 8; r++) {
                int c = cb * 8 + r;
                float4 v = *(const float4*)(stg + c * 1024 + qq * 16);
                ssq4[0] = fmaf(v.x, v.x, ssq4[0]);
                ssq4[1] = fmaf(v.y, v.y, ssq4[1]);
                ssq4[2] = fmaf(v.z, v.z, ssq4[2]);
                ssq4[3] = fmaf(v.w, v.w, ssq4[3]);
                __nv_bfloat162 h01 = __floats2bfloat162_rn(v.x, v.y);
                __nv_bfloat162 h23 = __floats2bfloat162_rn(v.z, v.w);
                unsigned off = (unsigned)(c * 512 + qq * 8);
                sts_v2(xbuf + (off ^ ((off >> 5) & 0x70)), h01, h23);
                uint2 u; u.x = *(unsigned*)&h01; u.y = *(unsigned*)&h23;
                *(uint2*)(xbo + (size_t)(ch * 32 + c) * NDIM) = u;
            }
        }
        __syncthreads();
        if (ch + 3 < 16) P1_ISSUE(ch % 3, ch + 3);
        CP_COMMIT();

        // MMA: 2 k-steps of 16 c over xbuf vs resident W
        const unsigned xbuf = sb + P1_XBUF + (unsigned)(ch & 1) * 16384u;
        const unsigned wb = sb + P1_WOFF + (unsigned)(ch >> 1) * 10240u;
        #pragma unroll
        for (int ks = 0; ks < 2; ks++) {
            uint32_t a[2][4];
            #pragma unroll
            for (int mf = 0; mf < 2; mf++) {
                // A^T: [c][n] 512B rows; trans -> row-major n x c frags
                int crow = ks * 16 + (lane & 7) + ((lane >> 4) & 1) * 8;
                int ncol = wid * 32 + mf * 16 + ((lane >> 3) & 1) * 8;
                unsigned off = (unsigned)(crow * 512 + ncol * 2);
                ldsm_x4t(a[mf], xbuf + (off ^ ((off >> 5) & 0x70)));
            }
            const int kc = (ch & 1) * 2 + ks;    // 16-c step within 64-c W block
            #pragma unroll
            for (int nb = 0; nb < 5; nb++) {
                uint32_t bf[4];
                int trow = nb * 16 + ((lane >> 4) & 1) * 8 + (lane & 7);
                unsigned off = (unsigned)(trow * 128 + kc * 32 + ((lane >> 3) & 1) * 16);
                ldsm_x4(bf, wb + (off ^ ((off >> 3) & 0x70)));
                #pragma unroll
                for (int mf = 0; mf < 2; mf++) {
                    mma_bf16(acc[mf][2 * nb],     a[mf], &bf[0]);
                    mma_bf16(acc[mf][2 * nb + 1], a[mf], &bf[2]);
                }
            }
        }
    }

    // ssq partials -> invn  (layout [cb][qq][4]; flat index cb*256 + tid_low)
    *(float4*)(sm + P1_SSQS + (unsigned)tid * 16) =
        make_float4(ssq4[0], ssq4[1], ssq4[2], ssq4[3]);
    __syncthreads();
    {
        const float* fs = (const float*)(sm + P1_SSQS);
        float s = fs[tid] + fs[256 + tid] + fs[512 + tid] + fs[768 + tid];
        ((float*)(sm + P1_INVN))[tid] = 1.0f / fmaxf(sqrtf(s), 1e-12f);
    }
    __syncthreads();

    // fragments -> logits smem [256 n][84 t]
    {
        float* lg = (float*)(sm + P1_LG);
        const float* invn = (const float*)(sm + P1_INVN);
        const float* bias = (const float*)(sm + P1_BIAS);
        #pragma unroll
        for (int mf = 0; mf < 2; mf++) {
            int r0 = wid * 32 + mf * 16 + (lane >> 2);
            float i0 = invn[r0], i1 = invn[r0 + 8];
            #pragma unroll
            for (int nb = 0; nb < 10; nb++) {
                int tc = nb * 8 + 2 * (lane & 3);
                float b0 = bias[tc], b1 = bias[tc + 1];
                lg[r0 * 84 + tc]           = acc[mf][nb][0] * i0 + b0;
                lg[r0 * 84 + tc + 1]       = acc[mf][nb][1] * i0 + b1;
                lg[(r0 + 8) * 84 + tc]     = acc[mf][nb][2] * i1 + b0;
                lg[(r0 + 8) * 84 + tc + 1] = acc[mf][nb][3] * i1 + b1;
            }
        }
    }
    __syncthreads();

    // softmax per n (all 256 threads); a2 (bf16) into staging
    {
        float* row = (float*)(sm + P1_LG) + tid * 84;
        float invn_n = ((float*)(sm + P1_INVN))[tid];
        float mx = -1e30f;
        #pragma unroll 8
        for (int t = 0; t < TCL; t++) mx = fmaxf(mx, row[t]);
        float s = 0.0f;
        #pragma unroll 8
        for (int t = 0; t < TCL; t++) { float e = __expf(row[t] - mx); row[t] = e; s += e; }
        float inv_s = 1.0f / s;
        float a2s   = inv_s * invn_n;
        __nv_bfloat16* a2st = (__nv_bfloat16*)(sm + P1_A2ST);
        #pragma unroll 8
        for (int t = 0; t < TCL; t++) {
            float e = row[t];
            if (t < KCL) a2st[t * 256 + tid] = __float2bfloat16(e * a2s);
            row[t] = e * inv_s;
        }
    }
    __syncthreads();

    // coalesced a2 writeout: [64 k][256 n] bf16 = 32KB
    #pragma unroll
    for (int it = 0; it < 8; it++) {
        int idx = tid + 256 * it;
        int k = idx >> 5, q2 = idx & 31;
        *(uint4*)((char*)(g_a2h + ((size_t)(b * KCL + k)) * NDIM + n0) + 16 * q2)
            = *(const uint4*)(sm + P1_A2ST + k * 512 + 16 * q2);
    }
    // mass partials (k<64 only; ghosts never read downstream)
    if (tid < KCL) {
        const float* lg = (const float*)(sm + P1_LG);
        float m = 0.0f;
        #pragma unroll 8
        for (int n = 0; n < NT1; n++) m += lg[n * 84 + tid];
        g_massp[((size_t)b * NTILES + ntile) * KCL + tid] = m;
    }
#undef P1_ISSUE
}

// ---------------------------------------------------------------------------
// Pass 2: HMMA bf16, 4-stage cp.async pipeline, no conversions.
// D[c,k] = sum_n xb[c,n]*a2[k,n]; M=128(c) N=64(k) K=4096(n), 64-n chunks.
// ---------------------------------------------------------------------------
#define STG_SZ 24576u
#define B_OFF  16384u

__global__ __launch_bounds__(256) void pass2()
{
    extern __shared__ char smem[];
    const unsigned sbase = smem_u32(smem);
    const int ct   = blockIdx.x;
    const int b    = blockIdx.y;
    const int c0   = ct * 128;
    const int tid  = threadIdx.x;
    const int lane = tid & 31;
    const int wid  = tid >> 5;
    const int warp_m = (wid & 3) * 32;
    const int warp_n = (wid >> 2) * 32;

    const __nv_bfloat16* xsrc = g_xb + ((size_t)b * CDIM + c0) * NDIM;
    const __nv_bfloat16* asrc = g_a2h + (size_t)b * KCL * NDIM;

#define P2_ISSUE(ST, CH) do {                                                  \
        unsigned _buf = sbase + (unsigned)(ST) * STG_SZ;                       \
        _Pragma("unroll")                                                      \
        for (int r = 0; r < 4; r++) {                                          \
            int g = tid + 256 * r; int row = g >> 3, c16 = g & 7;              \
            unsigned off = (unsigned)(row * 128 + c16 * 16);                   \
            cpa16(_buf + (off ^ ((off >> 3) & 0x70)),                          \
                  xsrc + (size_t)row * NDIM + (CH) * 64 + c16 * 8);            \
        }                                                                      \
        _Pragma("unroll")                                                      \
        for (int r = 0; r < 2; r++) {                                          \
            int g = tid + 256 * r; int k = g >> 3, c16 = g & 7;                \
            unsigned off = (unsigned)(k * 128 + c16 * 16);                     \
            cpa16(_buf + B_OFF + (off ^ ((off >> 3) & 0x70)),                  \
                  asrc + (size_t)k * NDIM + (CH) * 64 + c16 * 8);              \
        }                                                                      \
    } while (0)

    P2_ISSUE(0, 0); CP_COMMIT();
    P2_ISSUE(1, 1); CP_COMMIT();
    P2_ISSUE(2, 2); CP_COMMIT();

    float acc[2][4][4];
    #pragma unroll
    for (int i = 0; i < 2; i++)
        #pragma unroll
        for (int j = 0; j < 4; j++)
            #pragma unroll
            for (int q = 0; q < 4; q++) acc[i][j][q] = 0.0f;

    for (int ch = 0; ch < 64; ch++) {
        asm volatile("cp.async.wait_group 2;" ::: "memory");
        __syncthreads();
        if (ch + 3 < 64) P2_ISSUE((ch + 3) & 3, ch + 3);
        CP_COMMIT();

        const unsigned buf = sbase + (unsigned)(ch & 3) * STG_SZ;
        #pragma unroll
        for (int ks = 0; ks < 4; ks++) {
            uint32_t ah[2][4], bh2[2][4];
            #pragma unroll
            for (int mf = 0; mf < 2; mf++) {
                unsigned off = (unsigned)((warp_m + mf * 16 + (lane & 15)) * 128
                                          + ks * 32 + (lane >> 4) * 16);
                ldsm_x4(ah[mf], buf + (off ^ ((off >> 3) & 0x70)));
            }
            #pragma unroll
            for (int np = 0; np < 2; np++) {
                unsigned off = (unsigned)((warp_n + np * 16 + (lane >> 4) * 8 + (lane & 7)) * 128
                                          + ks * 32 + ((lane >> 3) & 1) * 16);
                ldsm_x4(bh2[np], buf + B_OFF + (off ^ ((off >> 3) & 0x70)));
            }
            #pragma unroll
            for (int mf = 0; mf < 2; mf++)
                #pragma unroll
                for (int np = 0; np < 2; np++)
                    #pragma unroll
                    for (int h = 0; h < 2; h++)
                        mma_bf16(acc[mf][np * 2 + h], ah[mf], &bh2[np][2 * h]);
        }
    }

    const int bbase = b * KCL;
    #pragma unroll
    for (int mf = 0; mf < 2; mf++) {
        int row = c0 + warp_m + mf * 16 + (lane >> 2);
        #pragma unroll
        for (int nf = 0; nf < 4; nf++) {
            int k = warp_n + nf * 8 + (lane & 3) * 2;
            float* g0 = g_agg + (size_t)(bbase + k) * CDIM + row;
            g0[0]        = acc[mf][nf][0];
            g0[CDIM]     = acc[mf][nf][1];
            g0[8]        = acc[mf][nf][2];
            g0[CDIM + 8] = acc[mf][nf][3];
        }
    }
#undef P2_ISSUE
}

// ---------------------------------------------------------------------------
// Pass 3: v = agg - centroid*mass; out = v/(max(||v||,eps)*8)
// (attention, ghost weighting and global norm cancel algebraically)
// ---------------------------------------------------------------------------
__global__ __launch_bounds__(128) void pass3(const float* __restrict__ centroids,
                                             float* __restrict__ out)
{
    const int k   = blockIdx.x;
    const int b   = blockIdx.y;
    const int tid = threadIdx.x;

    __shared__ float s_mass;
    __shared__ float s_red[4];

    if (tid == 0) {
        float m = 0.0f;
        #pragma unroll
        for (int t = 0; t < NTILES; t++) m += g_massp[((size_t)b * NTILES + t) * KCL + k];
        s_mass = m;
    }
    __syncthreads();
    const float mass = s_mass;

    float v[4];
    float ssq = 0.0f;
    #pragma unroll
    for (int j = 0; j < 4; j++) {
        int c = tid + 128 * j;
        float val = g_agg[((size_t)b * KCL + k) * CDIM + c] - centroids[k * CDIM + c] * mass;
        v[j] = val;
        ssq = fmaf(val, val, ssq);
    }
    #pragma unroll
    for (int o = 16; o > 0; o >>= 1) ssq += __shfl_xor_sync(0xffffffffu, ssq, o);
    if ((tid & 31) == 0) s_red[tid >> 5] = ssq;
    __syncthreads();
    float tot = s_red[0] + s_red[1] + s_red[2] + s_red[3];
    float scale = 1.0f / (fmaxf(sqrtf(tot), 1e-12f) * 8.0f);
    #pragma unroll
    for (int j = 0; j < 4; j++)
        out[((size_t)b * KCL + k) * CDIM + tid + 128 * j] = v[j] * scale;
}

// ---------------------------------------------------------------------------
extern "C" void kernel_launch(void* const* d_in, const int* in_sizes, int n_in,
                              void* d_out, int out_size)
{
    const float* x         = (const float*)d_in[0];
    const float* centroids = (const float*)d_in[1];
    const float* conv_w    = (const float*)d_in[2];
    const float* conv_b    = (const float*)d_in[3];
    float* out = (float*)d_out;

    cudaFuncSetAttribute(pass1, cudaFuncAttributeMaxDynamicSharedMemorySize, P1_SMEM);
    cudaFuncSetAttribute(pass2, cudaFuncAttributeMaxDynamicSharedMemorySize, 98304);

    pass0w<<<1, 256>>>(conv_w);
    pass1<<<dim3(NTILES, BATCH), 256, P1_SMEM>>>(x, conv_b);
    pass2<<<dim3(4, BATCH), 256, 98304>>>();
    pass3<<<dim3(KCL, BATCH), 128>>>(centroids, out);
}

// round 12
// speedup vs baseline: 6.4402x; 1.0313x over previous
#include <cuda_runtime.h>
#include <cuda_bf16.h>
#include <math.h>
#include <stdint.h>

#define BATCH 32
#define CDIM  512
#define NDIM  4096
#define TCL   72
#define KCL   64
#define NT1   128
#define NTILES 32            // 4096/128

// Scratch (static device globals; no runtime allocation)
__device__ __nv_bfloat16 g_a2h[(size_t)BATCH * KCL * NDIM];   // assign*invn, bf16
__device__ __nv_bfloat16 g_xb[(size_t)BATCH * CDIM * NDIM];   // x in bf16 (for pass2)
__device__ __nv_bfloat16 g_wb[16 * 80 * 32];                  // W bf16 [chunk16][t(80)][c(32)]
__device__ float g_massp[(size_t)BATCH * NTILES * KCL];
__device__ float g_agg[(size_t)BATCH * KCL * CDIM];

__device__ __forceinline__ unsigned smem_u32(const void* p) {
    unsigned a;
    asm("{ .reg .u64 t; cvta.to.shared.u64 t, %1; cvt.u32.u64 %0, t; }" : "=r"(a) : "l"(p));
    return a;
}
__device__ __forceinline__ void ldsm_x4(uint32_t* r, unsigned addr) {
    asm volatile("ldmatrix.sync.aligned.m8n8.x4.shared.b16 {%0,%1,%2,%3}, [%4];"
                 : "=r"(r[0]), "=r"(r[1]), "=r"(r[2]), "=r"(r[3]) : "r"(addr));
}
__device__ __forceinline__ void ldsm_x4t(uint32_t* r, unsigned addr) {
    asm volatile("ldmatrix.sync.aligned.m8n8.x4.trans.shared.b16 {%0,%1,%2,%3}, [%4];"
                 : "=r"(r[0]), "=r"(r[1]), "=r"(r[2]), "=r"(r[3]) : "r"(addr));
}
__device__ __forceinline__ void mma_bf16(float* c, const uint32_t* a, const uint32_t* b) {
    asm volatile(
        "mma.sync.aligned.m16n8k16.row.col.f32.bf16.bf16.f32 "
        "{%0,%1,%2,%3},{%4,%5,%6,%7},{%8,%9},{%0,%1,%2,%3};"
        : "+f"(c[0]), "+f"(c[1]), "+f"(c[2]), "+f"(c[3])
        : "r"(a[0]), "r"(a[1]), "r"(a[2]), "r"(a[3]), "r"(b[0]), "r"(b[1]));
}
__device__ __forceinline__ void sts_v2(unsigned addr, __nv_bfloat162 p0, __nv_bfloat162 p1) {
    asm volatile("st.shared.v2.b32 [%0], {%1,%2};"
                 :: "r"(addr), "r"(*(unsigned*)&p0), "r"(*(unsigned*)&p1));
}
__device__ __forceinline__ void cpa16(unsigned dst, const void* src) {
    asm volatile("cp.async.cg.shared.global [%0], [%1], 16;" :: "r"(dst), "l"(src));
}
#define CP_COMMIT() asm volatile("cp.async.commit_group;")

// ---------------------------------------------------------------------------
// Pass 0w: W fp32 -> bf16 table [16 chunks][80 t][32 c] (tiny; grid 1)
// ---------------------------------------------------------------------------
__global__ __launch_bounds__(256) void pass0w(const float* __restrict__ conv_w)
{
    const int tid = threadIdx.x;
    for (int i = tid; i < 80 * 512; i += 256) {
        int t = i >> 9, c = i & 511;
        float v = (t < TCL) ? conv_w[t * CDIM + c] : 0.0f;
        g_wb[(c >> 5) * 2560 + t * 32 + (c & 31)] = __float2bfloat16(v);
    }
}

// ---------------------------------------------------------------------------
// Pass 1 (fused convert + HMMA GEMM + softmax), 2 blocks/SM:
// 4-stage cp.async (fp32 x 32c x 128n + W chunk 80t x 32c) -> convert (ssq,
// bf16 xbuf, g_xb writeout) -> MMA. Then invn, logits, softmax, a2, mass.
// W smem tile rows stride 80B -> conflict-free ldmatrix, no swizzle.
// ---------------------------------------------------------------------------
#define P1_STG   23040u       // per stage: x 16384 (rows 512B) + W 6656 @ +16384
#define P1_WOFF  16384u
#define P1_XBUF  92160u       // 2 x (32c x 128n bf16, 256B rows, swz >>4)
#define P1_SSQS  108544u      // [8 cg][32 g][4] fp32 = 4KB
#define P1_INVN  112640u      // 128 fp32
#define P1_BIAS  113152u      // 80 fp32
#define P1_SMEM  113472
#define P1_LG    0u           // phase B: [128 n][84 t] fp32 (43008B)
#define P1_A2ST  43008u       // [64 k][128 n] bf16 (16384B)

__global__ __launch_bounds__(256, 2) void pass1(const float* __restrict__ x,
                                                const float* __restrict__ conv_b)
{
    extern __shared__ char sm[];
    const unsigned sb = smem_u32(sm);
    const int ntile = blockIdx.x;
    const int b     = blockIdx.y;
    const int n0    = ntile * NT1;
    const int tid   = threadIdx.x;
    const int lane  = tid & 31;
    const int wid   = tid >> 5;
    const int m0    = wid * 16;

    if (tid < 80) {
        float v = (tid < TCL) ? conv_b[tid] : 0.0f;
        *(float*)(sm + P1_BIAS + tid * 4) = v;
    }

    const float* xsrc = x + (size_t)b * CDIM * NDIM + n0;

#define P1_ISSUE(ST, CH) do {                                                  \
        unsigned _buf = sb + (unsigned)(ST) * P1_STG;                          \
        const float* _xs = xsrc + (size_t)(CH) * 32 * NDIM;                    \
        _Pragma("unroll")                                                      \
        for (int r = 0; r < 4; r++) {                                          \
            int idx = tid + 256 * r;                                           \
            int c = idx >> 5, q = idx & 31;                                    \
            cpa16(_buf + (unsigned)(c * 512 + q * 16),                         \
                  _xs + (size_t)c * NDIM + 4 * q);                             \
        }                                                                      \
        const __nv_bfloat16* _ws = g_wb + (CH) * 2560;                         \
        _Pragma("unroll")                                                      \
        for (int r = 0; r < 2; r++) {                                          \
            int idx = tid + 256 * r;                                           \
            if (idx < 320) {                                                   \
                int t = idx >> 2, pc = idx & 3;                                \
                cpa16(_buf + P1_WOFF + (unsigned)(t * 80 + pc * 16),           \
                      _ws + t * 32 + pc * 8);                                  \
            }                                                                  \
        }                                                                      \
    } while (0)

    P1_ISSUE(0, 0); CP_COMMIT();
    P1_ISSUE(1, 1); CP_COMMIT();
    P1_ISSUE(2, 2); CP_COMMIT();

    float acc[10][4];
    #pragma unroll
    for (int i = 0; i < 10; i++)
        #pragma unroll
        for (int j = 0; j < 4; j++) acc[i][j] = 0.0f;
    float ssq4[4] = {0.f, 0.f, 0.f, 0.f};

    const int cg = tid >> 5;       // 0..7 (c sub-block of 4 rows)
    const int gq = tid & 31;       // float4 column (4 n)
    __nv_bfloat16* xbo = g_xb + (size_t)b * CDIM * NDIM + n0 + 4 * gq;

    for (int ch = 0; ch < 16; ch++) {
        asm volatile("cp.async.wait_group 2;" ::: "memory");
        __syncthreads();

        // convert: fp32 stage -> ssq + bf16 xbuf + g_xb
        {
            const char* stg = sm + (unsigned)(ch & 3) * P1_STG;
            const unsigned xbuf = sb + P1_XBUF + (unsigned)(ch & 1) * 8192u;
            #pragma unroll
            for (int r = 0; r < 4; r++) {
                int c = cg * 4 + r;
                float4 v = *(const float4*)(stg + c * 512 + gq * 16);
                ssq4[0] = fmaf(v.x, v.x, ssq4[0]);
                ssq4[1] = fmaf(v.y, v.y, ssq4[1]);
                ssq4[2] = fmaf(v.z, v.z, ssq4[2]);
                ssq4[3] = fmaf(v.w, v.w, ssq4[3]);
                __nv_bfloat162 h01 = __floats2bfloat162_rn(v.x, v.y);
                __nv_bfloat162 h23 = __floats2bfloat162_rn(v.z, v.w);
                unsigned off = (unsigned)(c * 256 + gq * 8);
                sts_v2(xbuf + (off ^ ((off >> 4) & 0x70)), h01, h23);
                uint2 u; u.x = *(unsigned*)&h01; u.y = *(unsigned*)&h23;
                *(uint2*)(xbo + (size_t)(ch * 32 + c) * NDIM) = u;
            }
        }
        __syncthreads();
        if (ch + 3 < 16) P1_ISSUE((ch + 3) & 3, ch + 3);
        CP_COMMIT();

        // MMA: 2 k-steps of 16 c over xbuf vs this chunk's W tile
        const unsigned xbuf = sb + P1_XBUF + (unsigned)(ch & 1) * 8192u;
        const unsigned wst  = sb + (unsigned)(ch & 3) * P1_STG + P1_WOFF;
        #pragma unroll
        for (int ks = 0; ks < 2; ks++) {
            uint32_t a[4];
            {   // A^T: [c][n] 256B rows; trans -> row-major n x c frags
                int crow = ks * 16 + (lane & 7) + ((lane >> 4) & 1) * 8;
                int ncol = m0 + ((lane >> 3) & 1) * 8;
                unsigned off = (unsigned)(crow * 256 + ncol * 2);
                ldsm_x4t(a, xbuf + (off ^ ((off >> 4) & 0x70)));
            }
            #pragma unroll
            for (int nb = 0; nb < 5; nb++) {
                uint32_t bf[4];
                int trow = nb * 16 + ((lane >> 4) & 1) * 8 + (lane & 7);
                unsigned addr = wst + (unsigned)(trow * 80 + ks * 32
                                                 + ((lane >> 3) & 1) * 16);
                ldsm_x4(bf, addr);    // stride-80B rows: conflict-free, no swz
                mma_bf16(acc[2 * nb],     a, &bf[0]);
                mma_bf16(acc[2 * nb + 1], a, &bf[2]);
            }
        }
    }

    // ssq partials -> invn (layout [cg][gq][4]; flat = tid*4)
    *(float4*)(sm + P1_SSQS + (unsigned)tid * 16) =
        make_float4(ssq4[0], ssq4[1], ssq4[2], ssq4[3]);
    __syncthreads();
    if (tid < 128) {
        const float* fs = (const float*)(sm + P1_SSQS);
        float s = 0.0f;
        #pragma unroll
        for (int w2 = 0; w2 < 8; w2++) s += fs[w2 * 128 + tid];
        ((float*)(sm + P1_INVN))[tid] = 1.0f / fmaxf(sqrtf(s), 1e-12f);
    }
    __syncthreads();

    // fragments -> logits smem [128 n][84 t]
    {
        float* lg = (float*)(sm + P1_LG);
        const float* invn = (const float*)(sm + P1_INVN);
        const float* bias = (const float*)(sm + P1_BIAS);
        int r0 = m0 + (lane >> 2);
        float i0 = invn[r0], i1 = invn[r0 + 8];
        #pragma unroll
        for (int nb = 0; nb < 10; nb++) {
            int tc = nb * 8 + 2 * (lane & 3);
            float b0 = bias[tc], b1 = bias[tc + 1];
            lg[r0 * 84 + tc]           = acc[nb][0] * i0 + b0;
            lg[r0 * 84 + tc + 1]       = acc[nb][1] * i0 + b1;
            lg[(r0 + 8) * 84 + tc]     = acc[nb][2] * i1 + b0;
            lg[(r0 + 8) * 84 + tc + 1] = acc[nb][3] * i1 + b1;
        }
    }
    __syncthreads();

    // softmax per n; a2 (bf16) into staging
    if (tid < 128) {
        float* row = (float*)(sm + P1_LG) + tid * 84;
        float invn_n = ((float*)(sm + P1_INVN))[tid];
        float mx = -1e30f;
        #pragma unroll 8
        for (int t = 0; t < TCL; t++) mx = fmaxf(mx, row[t]);
        float s = 0.0f;
        #pragma unroll 8
        for (int t = 0; t < TCL; t++) { float e = __expf(row[t] - mx); row[t] = e; s += e; }
        float inv_s = 1.0f / s;
        float a2s   = inv_s * invn_n;
        __nv_bfloat16* a2st = (__nv_bfloat16*)(sm + P1_A2ST);
        #pragma unroll 8
        for (int t = 0; t < TCL; t++) {
            float e = row[t];
            if (t < KCL) a2st[t * 128 + tid] = __float2bfloat16(e * a2s);
            row[t] = e * inv_s;
        }
    }
    __syncthreads();

    // coalesced a2 writeout: [64 k][128 n] bf16 = 16KB
    #pragma unroll
    for (int it = 0; it < 4; it++) {
        int idx = tid + 256 * it;
        int k = idx >> 4, q2 = idx & 15;
        *(uint4*)((char*)(g_a2h + ((size_t)(b * KCL + k)) * NDIM + n0) + 16 * q2)
            = *(const uint4*)(sm + P1_A2ST + k * 256 + 16 * q2);
    }
    // mass partials (k<64 only; ghosts never read downstream)
    if (tid < KCL) {
        const float* lg = (const float*)(sm + P1_LG);
        float m = 0.0f;
        #pragma unroll 8
        for (int n = 0; n < NT1; n++) m += lg[n * 84 + tid];
        g_massp[((size_t)b * NTILES + ntile) * KCL + tid] = m;
    }
#undef P1_ISSUE
}

// ---------------------------------------------------------------------------
// Pass 2: HMMA bf16, 4-stage cp.async pipeline, no conversions.
// D[c,k] = sum_n xb[c,n]*a2[k,n]; M=128(c) N=64(k) K=4096(n), 64-n chunks.
// ---------------------------------------------------------------------------
#define STG_SZ 24576u
#define B_OFF  16384u

__global__ __launch_bounds__(256) void pass2()
{
    extern __shared__ char smem[];
    const unsigned sbase = smem_u32(smem);
    const int ct   = blockIdx.x;
    const int b    = blockIdx.y;
    const int c0   = ct * 128;
    const int tid  = threadIdx.x;
    const int lane = tid & 31;
    const int wid  = tid >> 5;
    const int warp_m = (wid & 3) * 32;
    const int warp_n = (wid >> 2) * 32;

    const __nv_bfloat16* xsrc = g_xb + ((size_t)b * CDIM + c0) * NDIM;
    const __nv_bfloat16* asrc = g_a2h + (size_t)b * KCL * NDIM;

#define P2_ISSUE(ST, CH) do {                                                  \
        unsigned _buf = sbase + (unsigned)(ST) * STG_SZ;                       \
        _Pragma("unroll")                                                      \
        for (int r = 0; r < 4; r++) {                                          \
            int g = tid + 256 * r; int row = g >> 3, c16 = g & 7;              \
            unsigned off = (unsigned)(row * 128 + c16 * 16);                   \
            cpa16(_buf + (off ^ ((off >> 3) & 0x70)),                          \
                  xsrc + (size_t)row * NDIM + (CH) * 64 + c16 * 8);            \
        }                                                                      \
        _Pragma("unroll")                                                      \
        for (int r = 0; r < 2; r++) {                                          \
            int g = tid + 256 * r; int k = g >> 3, c16 = g & 7;                \
            unsigned off = (unsigned)(k * 128 + c16 * 16);                     \
            cpa16(_buf + B_OFF + (off ^ ((off >> 3) & 0x70)),                  \
                  asrc + (size_t)k * NDIM + (CH) * 64 + c16 * 8);              \
        }                                                                      \
    } while (0)

    P2_ISSUE(0, 0); CP_COMMIT();
    P2_ISSUE(1, 1); CP_COMMIT();
    P2_ISSUE(2, 2); CP_COMMIT();

    float acc[2][4][4];
    #pragma unroll
    for (int i = 0; i < 2; i++)
        #pragma unroll
        for (int j = 0; j < 4; j++)
            #pragma unroll
            for (int q = 0; q < 4; q++) acc[i][j][q] = 0.0f;

    for (int ch = 0; ch < 64; ch++) {
        asm volatile("cp.async.wait_group 2;" ::: "memory");
        __syncthreads();
        if (ch + 3 < 64) P2_ISSUE((ch + 3) & 3, ch + 3);
        CP_COMMIT();

        const unsigned buf = sbase + (unsigned)(ch & 3) * STG_SZ;
        #pragma unroll
        for (int ks = 0; ks < 4; ks++) {
            uint32_t ah[2][4], bh2[2][4];
            #pragma unroll
            for (int mf = 0; mf < 2; mf++) {
                unsigned off = (unsigned)((warp_m + mf * 16 + (lane & 15)) * 128
                                          + ks * 32 + (lane >> 4) * 16);
                ldsm_x4(ah[mf], buf + (off ^ ((off >> 3) & 0x70)));
            }
            #pragma unroll
            for (int np = 0; np < 2; np++) {
                unsigned off = (unsigned)((warp_n + np * 16 + (lane >> 4) * 8 + (lane & 7)) * 128
                                          + ks * 32 + ((lane >> 3) & 1) * 16);
                ldsm_x4(bh2[np], buf + B_OFF + (off ^ ((off >> 3) & 0x70)));
            }
            #pragma unroll
            for (int mf = 0; mf < 2; mf++)
                #pragma unroll
                for (int np = 0; np < 2; np++)
                    #pragma unroll
                    for (int h = 0; h < 2; h++)
                        mma_bf16(acc[mf][np * 2 + h], ah[mf], &bh2[np][2 * h]);
        }
    }

    const int bbase = b * KCL;
    #pragma unroll
    for (int mf = 0; mf < 2; mf++) {
        int row = c0 + warp_m + mf * 16 + (lane >> 2);
        #pragma unroll
        for (int nf = 0; nf < 4; nf++) {
            int k = warp_n + nf * 8 + (lane & 3) * 2;
            float* g0 = g_agg + (size_t)(bbase + k) * CDIM + row;
            g0[0]        = acc[mf][nf][0];
            g0[CDIM]     = acc[mf][nf][1];
            g0[8]        = acc[mf][nf][2];
            g0[CDIM + 8] = acc[mf][nf][3];
        }
    }
#undef P2_ISSUE
}

// ---------------------------------------------------------------------------
// Pass 3: v = agg - centroid*mass; out = v/(max(||v||,eps)*8)
// (attention, ghost weighting and global norm cancel algebraically)
// ---------------------------------------------------------------------------
__global__ __launch_bounds__(128) void pass3(const float* __restrict__ centroids,
                                             float* __restrict__ out)
{
    const int k   = blockIdx.x;
    const int b   = blockIdx.y;
    const int tid = threadIdx.x;

    __shared__ float s_mass;
    __shared__ float s_red[4];

    if (tid == 0) {
        float m = 0.0f;
        #pragma unroll
        for (int t = 0; t < NTILES; t++) m += g_massp[((size_t)b * NTILES + t) * KCL + k];
        s_mass = m;
    }
    __syncthreads();
    const float mass = s_mass;

    float v[4];
    float ssq = 0.0f;
    #pragma unroll
    for (int j = 0; j < 4; j++) {
        int c = tid + 128 * j;
        float val = g_agg[((size_t)b * KCL + k) * CDIM + c] - centroids[k * CDIM + c] * mass;
        v[j] = val;
        ssq = fmaf(val, val, ssq);
    }
    #pragma unroll
    for (int o = 16; o > 0; o >>= 1) ssq += __shfl_xor_sync(0xffffffffu, ssq, o);
    if ((tid & 31) == 0) s_red[tid >> 5] = ssq;
    __syncthreads();
    float tot = s_red[0] + s_red[1] + s_red[2] + s_red[3];
    float scale = 1.0f / (fmaxf(sqrtf(tot), 1e-12f) * 8.0f);
    #pragma unroll
    for (int j = 0; j < 4; j++)
        out[((size_t)b * KCL + k) * CDIM + tid + 128 * j] = v[j] * scale;
}

// ---------------------------------------------------------------------------
extern "C" void kernel_launch(void* const* d_in, const int* in_sizes, int n_in,
                              void* d_out, int out_size)
{
    const float* x         = (const float*)d_in[0];
    const float* centroids = (const float*)d_in[1];
    const float* conv_w    = (const float*)d_in[2];
    const float* conv_b    = (const float*)d_in[3];
    float* out = (float*)d_out;

    cudaFuncSetAttribute(pass1, cudaFuncAttributeMaxDynamicSharedMemorySize, P1_SMEM);
    cudaFuncSetAttribute(pass2, cudaFuncAttributeMaxDynamicSharedMemorySize, 98304);

    pass0w<<<1, 256>>>(conv_w);
    pass1<<<dim3(NTILES, BATCH), 256, P1_SMEM>>>(x, conv_b);
    pass2<<<dim3(4, BATCH), 256, 98304>>>();
    pass3<<<dim3(KCL, BATCH), 128>>>(centroids, out);
}